// round 1
// baseline (speedup 1.0000x reference)
#include <cuda_runtime.h>
#include <math.h>

// Problem shape (fixed per reference setup_inputs)
#define Bn 8
#define Cn 512
#define Tn 2048
#define Gn 32
#define CPG (Cn / Gn)          // 16 channels per group
#define CT ((size_t)Cn * Tn)   // per-batch plane, 1M elements
#define TT ((size_t)Tn * Tn)   // per-batch scores, 4M elements

// Scratch (static __device__ globals — allocation-guard safe)
__device__ float g_h[Bn * Cn * Tn];   // group-normed input
__device__ float g_q[Bn * Cn * Tn];
__device__ float g_k[Bn * Cn * Tn];
__device__ float g_v[Bn * Cn * Tn];
__device__ float g_s[(size_t)Bn * Tn * Tn];  // scores / softmax weights (134 MB)
__device__ float g_a[Bn * Cn * Tn];   // attention output before o-proj

// ---------------------------------------------------------------------------
// GroupNorm: one block per (batch, group). Group = 16 channels x 2048 = 32768
// contiguous floats. Two passes over a contiguous 128KB span (L2-resident
// between passes).
// ---------------------------------------------------------------------------
__global__ void groupnorm_kernel(const float* __restrict__ x,
                                 const float* __restrict__ gamma,
                                 const float* __restrict__ beta) {
    const int bg = blockIdx.x;
    const int b = bg / Gn, g = bg % Gn;
    const size_t base = ((size_t)b * Cn + (size_t)g * CPG) * Tn;
    const int n = CPG * Tn;  // 32768
    const float4* xv = (const float4*)(x + base);

    float s = 0.f, ss = 0.f;
    for (int i = threadIdx.x; i < n / 4; i += blockDim.x) {
        float4 v = xv[i];
        s  += v.x + v.y + v.z + v.w;
        ss += v.x * v.x + v.y * v.y + v.z * v.z + v.w * v.w;
    }
    __shared__ float rs[256], rss[256];
    rs[threadIdx.x] = s; rss[threadIdx.x] = ss;
    __syncthreads();
    for (int o = 128; o > 0; o >>= 1) {
        if (threadIdx.x < o) {
            rs[threadIdx.x]  += rs[threadIdx.x + o];
            rss[threadIdx.x] += rss[threadIdx.x + o];
        }
        __syncthreads();
    }
    const float mean = rs[0] / n;
    const float var  = rss[0] / n - mean * mean;
    const float inv  = rsqrtf(var + 1e-6f);

    float4* hv = (float4*)(g_h + base);
    for (int i = threadIdx.x; i < n / 4; i += blockDim.x) {
        const int c = g * CPG + (i * 4) / Tn;  // all 4 lanes same channel (Tn%4==0)
        const float ga = gamma[c] * inv;
        const float be = beta[c] - mean * ga;
        float4 v = xv[i], o;
        o.x = v.x * ga + be; o.y = v.y * ga + be;
        o.z = v.z * ga + be; o.w = v.w * ga + be;
        hv[i] = o;
    }
}

// ---------------------------------------------------------------------------
// Generic batched tiled SGEMM: C = scale * op(A) * op(B) [+ bias[m]] [+ res]
// TA=0: A[m,k] at A[m*lda+k]   TA=1: A[m,k] at A[k*lda+m]
// TB=0: B[k,n] at B[k*ldb+n]   TB=1: B[k,n] at B[n*ldb+k]
// Block tile 128x128, K-tile 8, 256 threads, 8x8 per thread.
// Requires M%128==0, N%128==0, K%8==0 (all shapes here comply).
// ---------------------------------------------------------------------------
template <int TA, int TB, bool HAS_BIAS, bool HAS_RES>
__global__ __launch_bounds__(256, 2) void gemm_kernel(
    const float* __restrict__ A, const float* __restrict__ Bm,
    float* __restrict__ Cm,
    int M, int N, int K, int lda, int ldb, int ldc,
    size_t sA, size_t sB, size_t sC,
    const float* __restrict__ bias,
    const float* __restrict__ res, size_t sRes,
    float scale) {
    A  += (size_t)blockIdx.z * sA;
    Bm += (size_t)blockIdx.z * sB;
    Cm += (size_t)blockIdx.z * sC;
    if (HAS_RES) res += (size_t)blockIdx.z * sRes;

    __shared__ float As[8][128];
    __shared__ float Bs[8][128];

    const int tid = threadIdx.x;
    const int m0 = blockIdx.y * 128;
    const int n0 = blockIdx.x * 128;
    const int tx = tid & 15, ty = tid >> 4;

    float acc[8][8];
#pragma unroll
    for (int i = 0; i < 8; i++)
#pragma unroll
        for (int j = 0; j < 8; j++) acc[i][j] = 0.f;

    for (int k0 = 0; k0 < K; k0 += 8) {
        if (TA == 0) {
            const int row = tid >> 1, kc = (tid & 1) * 4;
            float4 v = *(const float4*)&A[(size_t)(m0 + row) * lda + k0 + kc];
            As[kc + 0][row] = v.x; As[kc + 1][row] = v.y;
            As[kc + 2][row] = v.z; As[kc + 3][row] = v.w;
        } else {
            const int kk = tid >> 5, mc = (tid & 31) * 4;
            *(float4*)&As[kk][mc] =
                *(const float4*)&A[(size_t)(k0 + kk) * lda + m0 + mc];
        }
        if (TB == 0) {
            const int kk = tid >> 5, nc = (tid & 31) * 4;
            *(float4*)&Bs[kk][nc] =
                *(const float4*)&Bm[(size_t)(k0 + kk) * ldb + n0 + nc];
        } else {
            const int row = tid >> 1, kc = (tid & 1) * 4;
            float4 v = *(const float4*)&Bm[(size_t)(n0 + row) * ldb + k0 + kc];
            Bs[kc + 0][row] = v.x; Bs[kc + 1][row] = v.y;
            Bs[kc + 2][row] = v.z; Bs[kc + 3][row] = v.w;
        }
        __syncthreads();
#pragma unroll
        for (int kk = 0; kk < 8; kk++) {
            float a[8], b[8];
            *(float4*)&a[0] = *(float4*)&As[kk][ty * 8];
            *(float4*)&a[4] = *(float4*)&As[kk][ty * 8 + 4];
            *(float4*)&b[0] = *(float4*)&Bs[kk][tx * 8];
            *(float4*)&b[4] = *(float4*)&Bs[kk][tx * 8 + 4];
#pragma unroll
            for (int i = 0; i < 8; i++)
#pragma unroll
                for (int j = 0; j < 8; j++) acc[i][j] += a[i] * b[j];
        }
        __syncthreads();
    }

#pragma unroll
    for (int i = 0; i < 8; i++) {
        const int m = m0 + ty * 8 + i;
        const float bv = HAS_BIAS ? bias[m] : 0.f;
#pragma unroll
        for (int j = 0; j < 8; j += 4) {
            const int n = n0 + tx * 8 + j;
            float4 o;
            o.x = acc[i][j + 0] * scale + bv;
            o.y = acc[i][j + 1] * scale + bv;
            o.z = acc[i][j + 2] * scale + bv;
            o.w = acc[i][j + 3] * scale + bv;
            if (HAS_RES) {
                float4 r = *(const float4*)&res[(size_t)m * ldc + n];
                o.x += r.x; o.y += r.y; o.z += r.z; o.w += r.w;
            }
            *(float4*)&Cm[(size_t)m * ldc + n] = o;
        }
    }
}

// ---------------------------------------------------------------------------
// Row softmax over scores: one block per row (B*T rows, each length T=2048).
// 256 threads x 8 elements held in registers; single read + single write.
// ---------------------------------------------------------------------------
__global__ void softmax_kernel() {
    float* p = g_s + (size_t)blockIdx.x * Tn;
    float4* pv = (float4*)p;
    const int tid = threadIdx.x;

    float4 v0 = pv[tid], v1 = pv[tid + 256];
    float mx = fmaxf(fmaxf(fmaxf(v0.x, v0.y), fmaxf(v0.z, v0.w)),
                     fmaxf(fmaxf(v1.x, v1.y), fmaxf(v1.z, v1.w)));
    __shared__ float red[256];
    red[tid] = mx;
    __syncthreads();
    for (int o = 128; o > 0; o >>= 1) {
        if (tid < o) red[tid] = fmaxf(red[tid], red[tid + o]);
        __syncthreads();
    }
    mx = red[0];
    __syncthreads();

    v0.x = __expf(v0.x - mx); v0.y = __expf(v0.y - mx);
    v0.z = __expf(v0.z - mx); v0.w = __expf(v0.w - mx);
    v1.x = __expf(v1.x - mx); v1.y = __expf(v1.y - mx);
    v1.z = __expf(v1.z - mx); v1.w = __expf(v1.w - mx);

    red[tid] = v0.x + v0.y + v0.z + v0.w + v1.x + v1.y + v1.z + v1.w;
    __syncthreads();
    for (int o = 128; o > 0; o >>= 1) {
        if (tid < o) red[tid] += red[tid + o];
        __syncthreads();
    }
    const float inv = 1.f / red[0];

    v0.x *= inv; v0.y *= inv; v0.z *= inv; v0.w *= inv;
    v1.x *= inv; v1.y *= inv; v1.z *= inv; v1.w *= inv;
    pv[tid] = v0;
    pv[tid + 256] = v1;
}

// ---------------------------------------------------------------------------
// Launch
// ---------------------------------------------------------------------------
static float* sym_addr(const void* s) {
    void* p = nullptr;
    cudaGetSymbolAddress(&p, s);
    return (float*)p;
}

extern "C" void kernel_launch(void* const* d_in, const int* in_sizes, int n_in,
                              void* d_out, int out_size) {
    const float* x     = (const float*)d_in[0];
    const float* gamma = (const float*)d_in[1];
    const float* beta  = (const float*)d_in[2];
    const float* q_w   = (const float*)d_in[3];
    const float* q_b   = (const float*)d_in[4];
    const float* k_w   = (const float*)d_in[5];
    const float* k_b   = (const float*)d_in[6];
    const float* v_w   = (const float*)d_in[7];
    const float* v_b   = (const float*)d_in[8];
    const float* o_w   = (const float*)d_in[9];
    const float* o_b   = (const float*)d_in[10];
    float* out = (float*)d_out;

    float* h = sym_addr(g_h);
    float* q = sym_addr(g_q);
    float* k = sym_addr(g_k);
    float* v = sym_addr(g_v);
    float* s = sym_addr(g_s);
    float* a = sym_addr(g_a);

    // 1) GroupNorm
    groupnorm_kernel<<<Bn * Gn, 256>>>(x, gamma, beta);

    // 2) Q/K/V projections: [C,T] = W[C,C] x h[C,T] + b   (NN)
    const dim3 gProj(Tn / 128, Cn / 128, Bn);
    gemm_kernel<0, 0, true, false><<<gProj, 256>>>(
        q_w, h, q, Cn, Tn, Cn, Cn, Tn, Tn, 0, CT, CT, q_b, nullptr, 0, 1.f);
    gemm_kernel<0, 0, true, false><<<gProj, 256>>>(
        k_w, h, k, Cn, Tn, Cn, Cn, Tn, Tn, 0, CT, CT, k_b, nullptr, 0, 1.f);
    gemm_kernel<0, 0, true, false><<<gProj, 256>>>(
        v_w, h, v, Cn, Tn, Cn, Cn, Tn, Tn, 0, CT, CT, v_b, nullptr, 0, 1.f);

    // 3) Scores: s[t,n] = scale * sum_c q[c,t] k[c,n]   (TN)
    const float scale = 1.f / sqrtf((float)Cn);
    const dim3 gScore(Tn / 128, Tn / 128, Bn);
    gemm_kernel<1, 0, false, false><<<gScore, 256>>>(
        q, k, s, Tn, Tn, Cn, Tn, Tn, Tn, CT, CT, TT, nullptr, nullptr, 0, scale);

    // 4) Softmax over last dim
    softmax_kernel<<<Bn * Tn, 256>>>();

    // 5) Attention output: a[c,t] = sum_sv v[c,sv] * w[t,sv]   (NT)
    const dim3 gAttn(Tn / 128, Cn / 128, Bn);
    gemm_kernel<0, 1, false, false><<<gAttn, 256>>>(
        v, s, a, Cn, Tn, Tn, Tn, Tn, Tn, CT, TT, CT, nullptr, nullptr, 0, 1.f);

    // 6) Output projection + bias + residual   (NN)
    gemm_kernel<0, 0, true, true><<<gAttn, 256>>>(
        o_w, a, out, Cn, Tn, Cn, Cn, Tn, Tn, 0, CT, CT, o_b, x, CT, 1.f);
}

// round 5
// speedup vs baseline: 2.8491x; 2.8491x over previous
#include <cuda_runtime.h>
#include <cuda_bf16.h>
#include <math.h>
#include <stdint.h>

#define Bn 8
#define Cn 512
#define Tn 2048
#define CT ((size_t)Cn * Tn)
#define TT ((size_t)Tn * Tn)

typedef __nv_bfloat16 bf16;

// ---------------- scratch (static device globals; allocation-guard safe) ----
// Flat [2][plane] arrays: index 0 = hi half, 1 = lo half. Host resolves the
// BASE symbol only (cudaGetSymbolAddress on an interior offset silently fails
// and returns garbage/null — that was the R3/R4 illegal-access bug).
__device__ __align__(16) bf16 g_hT[2][Bn * Tn * Cn];   // [B,T,C] hi/lo
__device__ __align__(16) bf16 g_wq[2][Cn * Cn];
__device__ __align__(16) bf16 g_wk[2][Cn * Cn];
__device__ __align__(16) bf16 g_wv[2][Cn * Cn];
__device__ __align__(16) bf16 g_wo[2][Cn * Cn];
__device__ __align__(16) bf16 g_qT[2][Bn * Tn * Cn];   // [B,T,C]
__device__ __align__(16) bf16 g_kT[2][Bn * Tn * Cn];   // [B,T,C]
__device__ __align__(16) bf16 g_vv[2][Bn * Cn * Tn];   // [B,C,T]
__device__ __align__(16) bf16 g_aT[2][Bn * Tn * Cn];   // [B,T,C]
__device__ __align__(16) float g_s[Bn * Tn * Tn];      // scores fp32 (134MB)
__device__ __align__(16) bf16 g_wt[2][Bn * Tn * Tn];   // softmax weights hi/lo
__device__ __align__(16) float g_mean[Bn * 32];
__device__ __align__(16) float g_inv[Bn * 32];

// ---------------- PTX helpers ----------------------------------------------
__device__ __forceinline__ uint32_t s2u(const void* p) {
    uint32_t a;
    asm("{ .reg .u64 t; cvta.to.shared.u64 t, %1; cvt.u32.u64 %0, t; }"
        : "=r"(a) : "l"(p));
    return a;
}

__device__ __forceinline__ void cp16(uint32_t d, const void* s) {
    asm volatile("cp.async.cg.shared.global [%0], [%1], 16;" :: "r"(d), "l"(s) : "memory");
}

#define LDSM4(r, addr)                                                          \
    asm volatile("ldmatrix.sync.aligned.m8n8.x4.shared.b16 {%0,%1,%2,%3}, [%4];"\
        : "=r"((r)[0]), "=r"((r)[1]), "=r"((r)[2]), "=r"((r)[3]) : "r"(addr))

#define MMA16816(d, a, b0, b1)                                                  \
    asm volatile(                                                               \
        "mma.sync.aligned.m16n8k16.row.col.f32.bf16.bf16.f32 "                  \
        "{%0,%1,%2,%3}, {%4,%5,%6,%7}, {%8,%9}, {%0,%1,%2,%3};"                 \
        : "+f"((d)[0]), "+f"((d)[1]), "+f"((d)[2]), "+f"((d)[3])                \
        : "r"((a)[0]), "r"((a)[1]), "r"((a)[2]), "r"((a)[3]),                   \
          "r"(b0), "r"(b1))

// ---------------- GroupNorm stats -------------------------------------------
__global__ void gn_stats(const float* __restrict__ x) {
    const int bg = blockIdx.x, tid = threadIdx.x;
    const int b = bg >> 5, g = bg & 31;
    const size_t base = ((size_t)b * Cn + g * 16) * Tn;
    const float4* xv = (const float4*)(x + base);
    float s = 0.f, ss = 0.f;
    for (int i = tid; i < 8192; i += 256) {
        float4 v = xv[i];
        s += v.x + v.y + v.z + v.w;
        ss += v.x * v.x + v.y * v.y + v.z * v.z + v.w * v.w;
    }
    __shared__ float rs[256], rq[256];
    rs[tid] = s; rq[tid] = ss;
    __syncthreads();
    for (int o = 128; o > 0; o >>= 1) {
        if (tid < o) { rs[tid] += rs[tid + o]; rq[tid] += rq[tid + o]; }
        __syncthreads();
    }
    if (tid == 0) {
        float mean = rs[0] / 32768.f;
        float var = rq[0] / 32768.f - mean * mean;
        g_mean[bg] = mean;
        g_inv[bg] = rsqrtf(var + 1e-6f);
    }
}

// ---------------- GN apply + transpose + bf16 split:  x[C,T] -> hT[T,C] -----
__global__ void hsplit(const float* __restrict__ x, const float* __restrict__ gamma,
                       const float* __restrict__ beta) {
    __shared__ float tl[32][33];
    const int b = blockIdx.z, t0 = blockIdx.x * 32, c0 = blockIdx.y * 32;
    const int tx = threadIdx.x, ty = threadIdx.y;
#pragma unroll
    for (int k = 0; k < 4; k++) {
        int c = c0 + ty + k * 8;
        float ga = gamma[c] * g_inv[b * 32 + (c >> 4)];
        float be = beta[c] - g_mean[b * 32 + (c >> 4)] * ga;
        float v = x[((size_t)b * Cn + c) * Tn + t0 + tx];
        tl[ty + k * 8][tx] = v * ga + be;
    }
    __syncthreads();
#pragma unroll
    for (int k = 0; k < 4; k++) {
        int t = t0 + ty + k * 8;
        float v = tl[tx][ty + k * 8];
        bf16 h = __float2bfloat16(v);
        size_t o = ((size_t)b * Tn + t) * Cn + c0 + tx;
        g_hT[0][o] = h;
        g_hT[1][o] = __float2bfloat16(v - __bfloat162float(h));
    }
}

// ---------------- generic fp32 -> bf16 hi/lo split --------------------------
__global__ void fsplit(const float* __restrict__ s, bf16* __restrict__ hi,
                       bf16* __restrict__ lo, int n) {
    int i = blockIdx.x * blockDim.x + threadIdx.x;
    if (i < n) {
        float v = s[i];
        bf16 h = __float2bfloat16(v);
        hi[i] = h;
        lo[i] = __float2bfloat16(v - __bfloat162float(h));
    }
}

// ---------------- row softmax + bf16 hi/lo split ----------------------------
__global__ void softmax_split() {
    const size_t ro = (size_t)blockIdx.x * Tn;
    const float4* pv = (const float4*)(g_s + ro);
    const int tid = threadIdx.x;
    float4 v0 = pv[tid], v1 = pv[tid + 256];
    float mx = fmaxf(fmaxf(fmaxf(v0.x, v0.y), fmaxf(v0.z, v0.w)),
                     fmaxf(fmaxf(v1.x, v1.y), fmaxf(v1.z, v1.w)));
    __shared__ float red[256];
    red[tid] = mx;
    __syncthreads();
    for (int o = 128; o > 0; o >>= 1) {
        if (tid < o) red[tid] = fmaxf(red[tid], red[tid + o]);
        __syncthreads();
    }
    mx = red[0];
    __syncthreads();
    v0.x = __expf(v0.x - mx); v0.y = __expf(v0.y - mx);
    v0.z = __expf(v0.z - mx); v0.w = __expf(v0.w - mx);
    v1.x = __expf(v1.x - mx); v1.y = __expf(v1.y - mx);
    v1.z = __expf(v1.z - mx); v1.w = __expf(v1.w - mx);
    red[tid] = v0.x + v0.y + v0.z + v0.w + v1.x + v1.y + v1.z + v1.w;
    __syncthreads();
    for (int o = 128; o > 0; o >>= 1) {
        if (tid < o) red[tid] += red[tid + o];
        __syncthreads();
    }
    const float inv = 1.f / red[0];
    float a0[4] = {v0.x * inv, v0.y * inv, v0.z * inv, v0.w * inv};
    float a1[4] = {v1.x * inv, v1.y * inv, v1.z * inv, v1.w * inv};
    __align__(8) bf16 h[4], l[4];
#pragma unroll
    for (int i = 0; i < 4; i++) {
        h[i] = __float2bfloat16(a0[i]);
        l[i] = __float2bfloat16(a0[i] - __bfloat162float(h[i]));
    }
    *(uint2*)(g_wt[0] + ro + 4 * tid) = *(uint2*)h;
    *(uint2*)(g_wt[1] + ro + 4 * tid) = *(uint2*)l;
#pragma unroll
    for (int i = 0; i < 4; i++) {
        h[i] = __float2bfloat16(a1[i]);
        l[i] = __float2bfloat16(a1[i] - __bfloat162float(h[i]));
    }
    *(uint2*)(g_wt[0] + ro + 1024 + 4 * tid) = *(uint2*)h;
    *(uint2*)(g_wt[1] + ro + 1024 + 4 * tid) = *(uint2*)l;
}

// ---------------- mma.sync split-bf16 GEMM ----------------------------------
// D[m,n] = scale * sum over 3 segs of A_seg[m,k]*B_seg[n,k]  (+bias +res)
// segs: (Ahi,Bhi), (Ahi,Blo), (Alo,Bhi) — exact-split fp32 emulation.
// CTA tile 128x128, BK=64, 8 warps (2m x 4n), warp tile 64x32.
// Both operands K-major; SMEM rows 128B with XOR-16B swizzle.
#define STG_A 16384
#define STG_AB 32768
#define SMEM_SZ (2 * STG_AB)   // 65536

template <int BIAS_MODE, bool HAS_RES, bool OUT_SPLIT>
__global__ __launch_bounds__(256, 2) void tgemm(
    const bf16* __restrict__ Ahi, const bf16* __restrict__ Alo,
    const bf16* __restrict__ Bhi, const bf16* __restrict__ Blo,
    float* __restrict__ Cf, bf16* __restrict__ Ohi, bf16* __restrict__ Olo,
    int K, int lda, int ldb, int ldc,
    size_t sA, size_t sB, size_t sC,
    const float* __restrict__ bias, const float* __restrict__ res, size_t sRes,
    float scale) {
    extern __shared__ char smem[];
    const uint32_t sb = s2u(smem);
    const int tid = threadIdx.x, wid = tid >> 5, lane = tid & 31;
    const int m0 = blockIdx.y * 128, n0 = blockIdx.x * 128, b = blockIdx.z;
    const int wm = (wid >> 2) * 64, wn = (wid & 3) * 32;

    const char* As[3];
    const char* Bs[3];
    As[0] = (const char*)(Ahi + (size_t)b * sA + (size_t)m0 * lda);
    As[1] = As[0];
    As[2] = (const char*)(Alo + (size_t)b * sA + (size_t)m0 * lda);
    Bs[0] = (const char*)(Bhi + (size_t)b * sB + (size_t)n0 * ldb);
    Bs[1] = (const char*)(Blo + (size_t)b * sB + (size_t)n0 * ldb);
    Bs[2] = Bs[0];

    const int KS = K >> 6, S = 3 * KS;
    const size_t la2 = (size_t)lda * 2, lb2 = (size_t)ldb * 2;

    auto load = [&](int s, int buf) {
        int seg = (s >= KS) + (s >= 2 * KS);
        size_t kb = (size_t)((s - seg * KS) << 7);  // k0*2 bytes
        const char* Ap = As[seg] + kb;
        const char* Bp = Bs[seg] + kb;
        uint32_t ab = sb + buf * STG_AB;
        uint32_t bb = ab + STG_A;
#pragma unroll
        for (int j = 0; j < 4; j++) {
            int g = tid + j * 256;
            int r = g >> 3, c = g & 7;
            uint32_t sw = (uint32_t)(r * 128 + ((c ^ (r & 7)) << 4));
            cp16(ab + sw, Ap + (size_t)r * la2 + c * 16);
            cp16(bb + sw, Bp + (size_t)r * lb2 + c * 16);
        }
    };

    float acc[4][4][4];
#pragma unroll
    for (int i = 0; i < 4; i++)
#pragma unroll
        for (int j = 0; j < 4; j++)
#pragma unroll
            for (int q = 0; q < 4; q++) acc[i][j][q] = 0.f;

    load(0, 0);
    asm volatile("cp.async.commit_group;");

    for (int s = 0; s < S; s++) {
        const int cur = s & 1;
        asm volatile("cp.async.wait_group 0;");
        __syncthreads();
        if (s + 1 < S) {
            load(s + 1, cur ^ 1);
            asm volatile("cp.async.commit_group;");
        }
        const uint32_t ab = sb + cur * STG_AB;
        const uint32_t bb = ab + STG_A;
#pragma unroll
        for (int kk = 0; kk < 4; kk++) {
            uint32_t af[4][4], bfr[2][4];
#pragma unroll
            for (int mi = 0; mi < 4; mi++) {
                int r = wm + mi * 16 + (lane & 15);
                int c = kk * 2 + (lane >> 4);
                LDSM4(af[mi], ab + r * 128 + ((c ^ (r & 7)) << 4));
            }
#pragma unroll
            for (int nj = 0; nj < 2; nj++) {
                int r = wn + nj * 16 + (lane & 7) + ((lane >> 4) << 3);
                int c = kk * 2 + ((lane >> 3) & 1);
                LDSM4(bfr[nj], bb + r * 128 + ((c ^ (r & 7)) << 4));
            }
#pragma unroll
            for (int mi = 0; mi < 4; mi++)
#pragma unroll
                for (int nj = 0; nj < 2; nj++) {
                    MMA16816(acc[mi][nj * 2 + 0], af[mi], bfr[nj][0], bfr[nj][1]);
                    MMA16816(acc[mi][nj * 2 + 1], af[mi], bfr[nj][2], bfr[nj][3]);
                }
        }
    }

    // ---------------- epilogue (register accumulators -> global) -----------
    const int qr = lane >> 2, qc = (lane & 3) * 2;
#pragma unroll
    for (int mi = 0; mi < 4; mi++) {
#pragma unroll
        for (int ni = 0; ni < 4; ni++) {
            const int mA = m0 + wm + mi * 16 + qr;
            const int nA = n0 + wn + ni * 8 + qc;
#pragma unroll
            for (int h = 0; h < 2; h++) {
                const int m = mA + h * 8;
                float v0 = acc[mi][ni][h * 2 + 0] * scale;
                float v1 = acc[mi][ni][h * 2 + 1] * scale;
                if (BIAS_MODE == 1) { float bv = bias[m]; v0 += bv; v1 += bv; }
                if (BIAS_MODE == 2) { v0 += bias[nA]; v1 += bias[nA + 1]; }
                const size_t go = (size_t)m * ldc + nA;
                if (OUT_SPLIT) {
                    bf16 h0 = __float2bfloat16(v0);
                    bf16 h1 = __float2bfloat16(v1);
                    bf16 l0 = __float2bfloat16(v0 - __bfloat162float(h0));
                    bf16 l1 = __float2bfloat16(v1 - __bfloat162float(h1));
                    __align__(4) bf16 ph[2] = {h0, h1};
                    __align__(4) bf16 pl[2] = {l0, l1};
                    *(uint32_t*)(Ohi + (size_t)b * sC + go) = *(uint32_t*)ph;
                    *(uint32_t*)(Olo + (size_t)b * sC + go) = *(uint32_t*)pl;
                } else {
                    if (HAS_RES) {
                        float2 r2 = *(const float2*)(res + (size_t)b * sRes + go);
                        v0 += r2.x; v1 += r2.y;
                    }
                    float2 o2 = {v0, v1};
                    *(float2*)(Cf + (size_t)b * sC + go) = o2;
                }
            }
        }
    }
}

// ---------------- launch ----------------------------------------------------
// Resolve the BASE symbol only; interior offsets computed host-side.
template <typename T>
static T* sym_base(const void* sym) {
    void* p = nullptr;
    cudaGetSymbolAddress(&p, sym);
    return (T*)p;
}

extern "C" void kernel_launch(void* const* d_in, const int* in_sizes, int n_in,
                              void* d_out, int out_size) {
    const float* x = (const float*)d_in[0];
    const float* gamma = (const float*)d_in[1];
    const float* beta = (const float*)d_in[2];
    const float* q_w = (const float*)d_in[3];
    const float* q_b = (const float*)d_in[4];
    const float* k_w = (const float*)d_in[5];
    const float* k_b = (const float*)d_in[6];
    const float* v_w = (const float*)d_in[7];
    const float* v_b = (const float*)d_in[8];
    const float* o_w = (const float*)d_in[9];
    const float* o_b = (const float*)d_in[10];
    float* out = (float*)d_out;

    cudaFuncSetAttribute(tgemm<2, false, true>, cudaFuncAttributeMaxDynamicSharedMemorySize, SMEM_SZ);
    cudaFuncSetAttribute(tgemm<1, false, true>, cudaFuncAttributeMaxDynamicSharedMemorySize, SMEM_SZ);
    cudaFuncSetAttribute(tgemm<0, false, false>, cudaFuncAttributeMaxDynamicSharedMemorySize, SMEM_SZ);
    cudaFuncSetAttribute(tgemm<0, false, true>, cudaFuncAttributeMaxDynamicSharedMemorySize, SMEM_SZ);
    cudaFuncSetAttribute(tgemm<1, true, false>, cudaFuncAttributeMaxDynamicSharedMemorySize, SMEM_SZ);

    const size_t PL = (size_t)Bn * Tn * Cn;  // bf16 plane (activations)
    const size_t PW = (size_t)Cn * Cn;       // bf16 plane (weights)
    const size_t PS = (size_t)Bn * Tn * Tn;  // bf16 plane (softmax weights)

    bf16* hT0 = sym_base<bf16>(g_hT); bf16* hT1 = hT0 + PL;
    bf16* wq0 = sym_base<bf16>(g_wq); bf16* wq1 = wq0 + PW;
    bf16* wk0 = sym_base<bf16>(g_wk); bf16* wk1 = wk0 + PW;
    bf16* wv0 = sym_base<bf16>(g_wv); bf16* wv1 = wv0 + PW;
    bf16* wo0 = sym_base<bf16>(g_wo); bf16* wo1 = wo0 + PW;
    bf16* qT0 = sym_base<bf16>(g_qT); bf16* qT1 = qT0 + PL;
    bf16* kT0 = sym_base<bf16>(g_kT); bf16* kT1 = kT0 + PL;
    bf16* vv0 = sym_base<bf16>(g_vv); bf16* vv1 = vv0 + PL;
    bf16* aT0 = sym_base<bf16>(g_aT); bf16* aT1 = aT0 + PL;
    bf16* wt0 = sym_base<bf16>(g_wt); bf16* wt1 = wt0 + PS;
    float* s = sym_base<float>(g_s);

    // GroupNorm stats + apply/transpose/split, weight splits
    gn_stats<<<Bn * 32, 256>>>(x);
    hsplit<<<dim3(Tn / 32, Cn / 32, Bn), dim3(32, 8)>>>(x, gamma, beta);
    const int wn = Cn * Cn;
    fsplit<<<(wn + 255) / 256, 256>>>(q_w, wq0, wq1, wn);
    fsplit<<<(wn + 255) / 256, 256>>>(k_w, wk0, wk1, wn);
    fsplit<<<(wn + 255) / 256, 256>>>(v_w, wv0, wv1, wn);
    fsplit<<<(wn + 255) / 256, 256>>>(o_w, wo0, wo1, wn);

    // Q/K: D[t,c_out] = sum_cin hT[t,cin] * Wq[c_out,cin] + b[c_out] -> qT hi/lo
    dim3 gQK(Cn / 128, Tn / 128, Bn);
    tgemm<2, false, true><<<gQK, 256, SMEM_SZ>>>(
        hT0, hT1, wq0, wq1, nullptr, qT0, qT1,
        Cn, Cn, Cn, Cn, CT, 0, CT, q_b, nullptr, 0, 1.f);
    tgemm<2, false, true><<<gQK, 256, SMEM_SZ>>>(
        hT0, hT1, wk0, wk1, nullptr, kT0, kT1,
        Cn, Cn, Cn, Cn, CT, 0, CT, k_b, nullptr, 0, 1.f);

    // V: D[c_out,t] = sum_cin Wv[c_out,cin] * hT[t,cin] + b[c_out] -> v [C,T] hi/lo
    dim3 gV(Tn / 128, Cn / 128, Bn);
    tgemm<1, false, true><<<gV, 256, SMEM_SZ>>>(
        wv0, wv1, hT0, hT1, nullptr, vv0, vv1,
        Cn, Cn, Cn, Tn, 0, CT, CT, v_b, nullptr, 0, 1.f);

    // Scores: D[t,u] = scale * sum_c qT[t,c] * kT[u,c] -> s fp32
    dim3 gS(Tn / 128, Tn / 128, Bn);
    tgemm<0, false, false><<<gS, 256, SMEM_SZ>>>(
        qT0, qT1, kT0, kT1, s, nullptr, nullptr,
        Cn, Cn, Cn, Tn, CT, CT, TT, nullptr, nullptr, 0,
        1.f / sqrtf((float)Cn));

    // Softmax rows -> w hi/lo
    softmax_split<<<Bn * Tn, 256>>>();

    // Attn*V: D[t,c] = sum_u w[t,u] * v[c,u] -> aT hi/lo
    dim3 gA(Cn / 128, Tn / 128, Bn);
    tgemm<0, false, true><<<gA, 256, SMEM_SZ>>>(
        wt0, wt1, vv0, vv1, nullptr, aT0, aT1,
        Tn, Tn, Tn, Cn, TT, CT, CT, nullptr, nullptr, 0, 1.f);

    // Out proj: D[c,t] = sum_cin Wo[c,cin] * aT[t,cin] + o_b[c] + x[c,t] -> out fp32
    dim3 gO(Tn / 128, Cn / 128, Bn);
    tgemm<1, true, false><<<gO, 256, SMEM_SZ>>>(
        wo0, wo1, aT0, aT1, out, nullptr, nullptr,
        Cn, Cn, Cn, Tn, 0, CT, CT, o_b, x, CT, 1.f);
}

// round 6
// speedup vs baseline: 2.9676x; 1.0416x over previous
#include <cuda_runtime.h>
#include <cuda_bf16.h>
#include <math.h>
#include <stdint.h>

#define Bn 8
#define Cn 512
#define Tn 2048
#define CT ((size_t)Cn * Tn)
#define TT ((size_t)Tn * Tn)

typedef __nv_bfloat16 bf16;

// ---------------- scratch (static device globals; allocation-guard safe) ----
// Flat [2][plane] arrays: index 0 = hi half, 1 = lo half. Host resolves the
// BASE symbol only (cudaGetSymbolAddress on an interior offset fails).
__device__ __align__(16) bf16 g_hT[2][Bn * Tn * Cn];   // [B,T,C] hi/lo
__device__ __align__(16) bf16 g_wq[2][Cn * Cn];
__device__ __align__(16) bf16 g_wk[2][Cn * Cn];
__device__ __align__(16) bf16 g_wv[2][Cn * Cn];
__device__ __align__(16) bf16 g_wo[2][Cn * Cn];
__device__ __align__(16) bf16 g_qT[2][Bn * Tn * Cn];   // [B,T,C]
__device__ __align__(16) bf16 g_kT[2][Bn * Tn * Cn];   // [B,T,C]
__device__ __align__(16) bf16 g_vv[2][Bn * Cn * Tn];   // [B,C,T]
__device__ __align__(16) bf16 g_aT[2][Bn * Tn * Cn];   // [B,T,C]
__device__ __align__(16) float g_s[Bn * Tn * Tn];      // scores fp32 (134MB)
__device__ __align__(16) bf16 g_wt[2][Bn * Tn * Tn];   // softmax weights hi/lo
__device__ __align__(16) float g_mean[Bn * 32];
__device__ __align__(16) float g_inv[Bn * 32];

// ---------------- PTX helpers ----------------------------------------------
__device__ __forceinline__ uint32_t s2u(const void* p) {
    uint32_t a;
    asm("{ .reg .u64 t; cvta.to.shared.u64 t, %1; cvt.u32.u64 %0, t; }"
        : "=r"(a) : "l"(p));
    return a;
}

__device__ __forceinline__ void cp16(uint32_t d, const void* s) {
    asm volatile("cp.async.cg.shared.global [%0], [%1], 16;" :: "r"(d), "l"(s) : "memory");
}

#define LDSM4(r, addr)                                                          \
    asm volatile("ldmatrix.sync.aligned.m8n8.x4.shared.b16 {%0,%1,%2,%3}, [%4];"\
        : "=r"((r)[0]), "=r"((r)[1]), "=r"((r)[2]), "=r"((r)[3]) : "r"(addr))

#define MMA16816(d, a, b0, b1)                                                  \
    asm volatile(                                                               \
        "mma.sync.aligned.m16n8k16.row.col.f32.bf16.bf16.f32 "                  \
        "{%0,%1,%2,%3}, {%4,%5,%6,%7}, {%8,%9}, {%0,%1,%2,%3};"                 \
        : "+f"((d)[0]), "+f"((d)[1]), "+f"((d)[2]), "+f"((d)[3])                \
        : "r"((a)[0]), "r"((a)[1]), "r"((a)[2]), "r"((a)[3]),                   \
          "r"(b0), "r"(b1))

// ---------------- GroupNorm stats -------------------------------------------
__global__ void gn_stats(const float* __restrict__ x) {
    const int bg = blockIdx.x, tid = threadIdx.x;
    const int b = bg >> 5, g = bg & 31;
    const size_t base = ((size_t)b * Cn + g * 16) * Tn;
    const float4* xv = (const float4*)(x + base);
    float s = 0.f, ss = 0.f;
    for (int i = tid; i < 8192; i += 256) {
        float4 v = xv[i];
        s += v.x + v.y + v.z + v.w;
        ss += v.x * v.x + v.y * v.y + v.z * v.z + v.w * v.w;
    }
    __shared__ float rs[256], rq[256];
    rs[tid] = s; rq[tid] = ss;
    __syncthreads();
    for (int o = 128; o > 0; o >>= 1) {
        if (tid < o) { rs[tid] += rs[tid + o]; rq[tid] += rq[tid + o]; }
        __syncthreads();
    }
    if (tid == 0) {
        float mean = rs[0] / 32768.f;
        float var = rq[0] / 32768.f - mean * mean;
        g_mean[bg] = mean;
        g_inv[bg] = rsqrtf(var + 1e-6f);
    }
}

// ---------------- GN apply + transpose + bf16 split:  x[C,T] -> hT[T,C] -----
__global__ void hsplit(const float* __restrict__ x, const float* __restrict__ gamma,
                       const float* __restrict__ beta) {
    __shared__ float tl[32][33];
    const int b = blockIdx.z, t0 = blockIdx.x * 32, c0 = blockIdx.y * 32;
    const int tx = threadIdx.x, ty = threadIdx.y;
#pragma unroll
    for (int k = 0; k < 4; k++) {
        int c = c0 + ty + k * 8;
        float ga = gamma[c] * g_inv[b * 32 + (c >> 4)];
        float be = beta[c] - g_mean[b * 32 + (c >> 4)] * ga;
        float v = x[((size_t)b * Cn + c) * Tn + t0 + tx];
        tl[ty + k * 8][tx] = v * ga + be;
    }
    __syncthreads();
#pragma unroll
    for (int k = 0; k < 4; k++) {
        int t = t0 + ty + k * 8;
        float v = tl[tx][ty + k * 8];
        bf16 h = __float2bfloat16(v);
        size_t o = ((size_t)b * Tn + t) * Cn + c0 + tx;
        g_hT[0][o] = h;
        g_hT[1][o] = __float2bfloat16(v - __bfloat162float(h));
    }
}

// ---------------- all 4 weight matrices -> bf16 hi/lo, one launch -----------
__global__ void wsplit(const float* __restrict__ qw, const float* __restrict__ kw,
                       const float* __restrict__ vw, const float* __restrict__ ow) {
    const int n = Cn * Cn;
    int i = blockIdx.x * blockDim.x + threadIdx.x;
    if (i >= 4 * n) return;
    int seg = i / n, j = i - seg * n;
    const float* src = (seg == 0) ? qw : (seg == 1) ? kw : (seg == 2) ? vw : ow;
    float v = src[j];
    bf16 h = __float2bfloat16(v);
    bf16 l = __float2bfloat16(v - __bfloat162float(h));
    bf16* hd = (seg == 0) ? g_wq[0] : (seg == 1) ? g_wk[0] : (seg == 2) ? g_wv[0] : g_wo[0];
    bf16* ld = (seg == 0) ? g_wq[1] : (seg == 1) ? g_wk[1] : (seg == 2) ? g_wv[1] : g_wo[1];
    hd[j] = h;
    ld[j] = l;
}

// ---------------- row softmax + bf16 hi/lo split ----------------------------
__global__ void softmax_split() {
    const size_t ro = (size_t)blockIdx.x * Tn;
    const float4* pv = (const float4*)(g_s + ro);
    const int tid = threadIdx.x;
    float4 v0 = pv[tid], v1 = pv[tid + 256];
    float mx = fmaxf(fmaxf(fmaxf(v0.x, v0.y), fmaxf(v0.z, v0.w)),
                     fmaxf(fmaxf(v1.x, v1.y), fmaxf(v1.z, v1.w)));
    __shared__ float red[256];
    red[tid] = mx;
    __syncthreads();
    for (int o = 128; o > 0; o >>= 1) {
        if (tid < o) red[tid] = fmaxf(red[tid], red[tid + o]);
        __syncthreads();
    }
    mx = red[0];
    __syncthreads();
    v0.x = __expf(v0.x - mx); v0.y = __expf(v0.y - mx);
    v0.z = __expf(v0.z - mx); v0.w = __expf(v0.w - mx);
    v1.x = __expf(v1.x - mx); v1.y = __expf(v1.y - mx);
    v1.z = __expf(v1.z - mx); v1.w = __expf(v1.w - mx);
    red[tid] = v0.x + v0.y + v0.z + v0.w + v1.x + v1.y + v1.z + v1.w;
    __syncthreads();
    for (int o = 128; o > 0; o >>= 1) {
        if (tid < o) red[tid] += red[tid + o];
        __syncthreads();
    }
    const float inv = 1.f / red[0];
    float a0[4] = {v0.x * inv, v0.y * inv, v0.z * inv, v0.w * inv};
    float a1[4] = {v1.x * inv, v1.y * inv, v1.z * inv, v1.w * inv};
    __align__(8) bf16 h[4], l[4];
#pragma unroll
    for (int i = 0; i < 4; i++) {
        h[i] = __float2bfloat16(a0[i]);
        l[i] = __float2bfloat16(a0[i] - __bfloat162float(h[i]));
    }
    *(uint2*)(g_wt[0] + ro + 4 * tid) = *(uint2*)h;
    *(uint2*)(g_wt[1] + ro + 4 * tid) = *(uint2*)l;
#pragma unroll
    for (int i = 0; i < 4; i++) {
        h[i] = __float2bfloat16(a1[i]);
        l[i] = __float2bfloat16(a1[i] - __bfloat162float(h[i]));
    }
    *(uint2*)(g_wt[0] + ro + 1024 + 4 * tid) = *(uint2*)h;
    *(uint2*)(g_wt[1] + ro + 1024 + 4 * tid) = *(uint2*)l;
}

// ---------------- mma.sync split-bf16 GEMM, 3-stage pipeline ----------------
// D[m,n] = scale * sum over 3 segs of A_seg[m,k]*B_seg[n,k]  (+bias +res)
// segs: (Ahi,Bhi), (Ahi,Blo), (Alo,Bhi) — exact-split fp32 emulation.
// CTA tile 128x128, BK=64, 8 warps (2m x 4n), warp tile 64x32.
// Both operands K-major; SMEM rows 128B with XOR-16B swizzle.
#define STG_A 16384
#define STG_AB 32768
#define NSTAGE 3
#define SMEM_SZ (NSTAGE * STG_AB)   // 98304

template <int BIAS_MODE, bool HAS_RES, bool OUT_SPLIT>
__global__ __launch_bounds__(256, 2) void tgemm(
    const bf16* __restrict__ Ahi, const bf16* __restrict__ Alo,
    const bf16* __restrict__ Bhi, const bf16* __restrict__ Blo,
    float* __restrict__ Cf, bf16* __restrict__ Ohi, bf16* __restrict__ Olo,
    int K, int lda, int ldb, int ldc,
    size_t sA, size_t sB, size_t sC,
    const float* __restrict__ bias, const float* __restrict__ res, size_t sRes,
    float scale) {
    extern __shared__ char smem[];
    const uint32_t sb = s2u(smem);
    const int tid = threadIdx.x, wid = tid >> 5, lane = tid & 31;
    const int m0 = blockIdx.y * 128, n0 = blockIdx.x * 128, b = blockIdx.z;
    const int wm = (wid >> 2) * 64, wn = (wid & 3) * 32;

    const char* As[3];
    const char* Bs[3];
    As[0] = (const char*)(Ahi + (size_t)b * sA + (size_t)m0 * lda);
    As[1] = As[0];
    As[2] = (const char*)(Alo + (size_t)b * sA + (size_t)m0 * lda);
    Bs[0] = (const char*)(Bhi + (size_t)b * sB + (size_t)n0 * ldb);
    Bs[1] = (const char*)(Blo + (size_t)b * sB + (size_t)n0 * ldb);
    Bs[2] = Bs[0];

    const int KS = K >> 6, S = 3 * KS;
    const size_t la2 = (size_t)lda * 2, lb2 = (size_t)ldb * 2;

    auto load = [&](int s, int buf) {
        int seg = (s >= KS) + (s >= 2 * KS);
        size_t kb = (size_t)((s - seg * KS) << 7);  // k0*2 bytes
        const char* Ap = As[seg] + kb;
        const char* Bp = Bs[seg] + kb;
        uint32_t ab = sb + buf * STG_AB;
        uint32_t bb = ab + STG_A;
#pragma unroll
        for (int j = 0; j < 4; j++) {
            int g = tid + j * 256;
            int r = g >> 3, c = g & 7;
            uint32_t sw = (uint32_t)(r * 128 + ((c ^ (r & 7)) << 4));
            cp16(ab + sw, Ap + (size_t)r * la2 + c * 16);
            cp16(bb + sw, Bp + (size_t)r * lb2 + c * 16);
        }
    };

    float acc[4][4][4];
#pragma unroll
    for (int i = 0; i < 4; i++)
#pragma unroll
        for (int j = 0; j < 4; j++)
#pragma unroll
            for (int q = 0; q < 4; q++) acc[i][j][q] = 0.f;

    // prologue: two stages in flight
    load(0, 0);
    asm volatile("cp.async.commit_group;");
    load(1, 1);
    asm volatile("cp.async.commit_group;");

    int cur = 0;
    for (int s = 0; s < S; s++) {
        asm volatile("cp.async.wait_group 1;");  // stage s landed
        __syncthreads();
        if (s + 2 < S) load(s + 2, (cur + 2) % NSTAGE);
        asm volatile("cp.async.commit_group;");  // (possibly empty) keeps accounting exact
        const uint32_t ab = sb + cur * STG_AB;
        const uint32_t bb = ab + STG_A;
#pragma unroll
        for (int kk = 0; kk < 4; kk++) {
            uint32_t af[4][4], bfr[2][4];
#pragma unroll
            for (int mi = 0; mi < 4; mi++) {
                int r = wm + mi * 16 + (lane & 15);
                int c = kk * 2 + (lane >> 4);
                LDSM4(af[mi], ab + r * 128 + ((c ^ (r & 7)) << 4));
            }
#pragma unroll
            for (int nj = 0; nj < 2; nj++) {
                int r = wn + nj * 16 + (lane & 7) + ((lane >> 4) << 3);
                int c = kk * 2 + ((lane >> 3) & 1);
                LDSM4(bfr[nj], bb + r * 128 + ((c ^ (r & 7)) << 4));
            }
#pragma unroll
            for (int mi = 0; mi < 4; mi++)
#pragma unroll
                for (int nj = 0; nj < 2; nj++) {
                    MMA16816(acc[mi][nj * 2 + 0], af[mi], bfr[nj][0], bfr[nj][1]);
                    MMA16816(acc[mi][nj * 2 + 1], af[mi], bfr[nj][2], bfr[nj][3]);
                }
        }
        cur = (cur + 1 == NSTAGE) ? 0 : cur + 1;
    }

    // ---------------- epilogue (register accumulators -> global) -----------
    const int qr = lane >> 2, qc = (lane & 3) * 2;
#pragma unroll
    for (int mi = 0; mi < 4; mi++) {
#pragma unroll
        for (int ni = 0; ni < 4; ni++) {
            const int mA = m0 + wm + mi * 16 + qr;
            const int nA = n0 + wn + ni * 8 + qc;
#pragma unroll
            for (int h = 0; h < 2; h++) {
                const int m = mA + h * 8;
                float v0 = acc[mi][ni][h * 2 + 0] * scale;
                float v1 = acc[mi][ni][h * 2 + 1] * scale;
                if (BIAS_MODE == 1) { float bv = bias[m]; v0 += bv; v1 += bv; }
                if (BIAS_MODE == 2) { v0 += bias[nA]; v1 += bias[nA + 1]; }
                const size_t go = (size_t)m * ldc + nA;
                if (OUT_SPLIT) {
                    bf16 h0 = __float2bfloat16(v0);
                    bf16 h1 = __float2bfloat16(v1);
                    bf16 l0 = __float2bfloat16(v0 - __bfloat162float(h0));
                    bf16 l1 = __float2bfloat16(v1 - __bfloat162float(h1));
                    __align__(4) bf16 ph[2] = {h0, h1};
                    __align__(4) bf16 pl[2] = {l0, l1};
                    *(uint32_t*)(Ohi + (size_t)b * sC + go) = *(uint32_t*)ph;
                    *(uint32_t*)(Olo + (size_t)b * sC + go) = *(uint32_t*)pl;
                } else {
                    if (HAS_RES) {
                        float2 r2 = *(const float2*)(res + (size_t)b * sRes + go);
                        v0 += r2.x; v1 += r2.y;
                    }
                    float2 o2 = {v0, v1};
                    *(float2*)(Cf + (size_t)b * sC + go) = o2;
                }
            }
        }
    }
}

// ---------------- launch ----------------------------------------------------
// Resolve the BASE symbol only; interior offsets computed host-side.
template <typename T>
static T* sym_base(const void* sym) {
    void* p = nullptr;
    cudaGetSymbolAddress(&p, sym);
    return (T*)p;
}

extern "C" void kernel_launch(void* const* d_in, const int* in_sizes, int n_in,
                              void* d_out, int out_size) {
    const float* x = (const float*)d_in[0];
    const float* gamma = (const float*)d_in[1];
    const float* beta = (const float*)d_in[2];
    const float* q_w = (const float*)d_in[3];
    const float* q_b = (const float*)d_in[4];
    const float* k_w = (const float*)d_in[5];
    const float* k_b = (const float*)d_in[6];
    const float* v_w = (const float*)d_in[7];
    const float* v_b = (const float*)d_in[8];
    const float* o_w = (const float*)d_in[9];
    const float* o_b = (const float*)d_in[10];
    float* out = (float*)d_out;

    cudaFuncSetAttribute(tgemm<2, false, true>, cudaFuncAttributeMaxDynamicSharedMemorySize, SMEM_SZ);
    cudaFuncSetAttribute(tgemm<1, false, true>, cudaFuncAttributeMaxDynamicSharedMemorySize, SMEM_SZ);
    cudaFuncSetAttribute(tgemm<0, false, false>, cudaFuncAttributeMaxDynamicSharedMemorySize, SMEM_SZ);
    cudaFuncSetAttribute(tgemm<0, false, true>, cudaFuncAttributeMaxDynamicSharedMemorySize, SMEM_SZ);
    cudaFuncSetAttribute(tgemm<1, true, false>, cudaFuncAttributeMaxDynamicSharedMemorySize, SMEM_SZ);

    const size_t PL = (size_t)Bn * Tn * Cn;  // bf16 plane (activations)
    const size_t PW = (size_t)Cn * Cn;       // bf16 plane (weights)
    const size_t PS = (size_t)Bn * Tn * Tn;  // bf16 plane (softmax weights)

    bf16* hT0 = sym_base<bf16>(g_hT); bf16* hT1 = hT0 + PL;
    bf16* wq0 = sym_base<bf16>(g_wq); bf16* wq1 = wq0 + PW;
    bf16* wk0 = sym_base<bf16>(g_wk); bf16* wk1 = wk0 + PW;
    bf16* wv0 = sym_base<bf16>(g_wv); bf16* wv1 = wv0 + PW;
    bf16* wo0 = sym_base<bf16>(g_wo); bf16* wo1 = wo0 + PW;
    bf16* qT0 = sym_base<bf16>(g_qT); bf16* qT1 = qT0 + PL;
    bf16* kT0 = sym_base<bf16>(g_kT); bf16* kT1 = kT0 + PL;
    bf16* vv0 = sym_base<bf16>(g_vv); bf16* vv1 = vv0 + PL;
    bf16* aT0 = sym_base<bf16>(g_aT); bf16* aT1 = aT0 + PL;
    bf16* wt0 = sym_base<bf16>(g_wt); bf16* wt1 = wt0 + PS;
    float* s = sym_base<float>(g_s);

    // 0: GN stats  1: GN apply+transpose+split  2: all weights split
    gn_stats<<<Bn * 32, 256>>>(x);
    hsplit<<<dim3(Tn / 32, Cn / 32, Bn), dim3(32, 8)>>>(x, gamma, beta);
    wsplit<<<(4 * Cn * Cn + 255) / 256, 256>>>(q_w, k_w, v_w, o_w);

    // 3,4: Q/K projections -> qT/kT hi/lo   (launch idx 5 = V GEMM, ncu target)
    dim3 gQK(Cn / 128, Tn / 128, Bn);
    tgemm<2, false, true><<<gQK, 256, SMEM_SZ>>>(
        hT0, hT1, wq0, wq1, nullptr, qT0, qT1,
        Cn, Cn, Cn, Cn, CT, 0, CT, q_b, nullptr, 0, 1.f);
    tgemm<2, false, true><<<gQK, 256, SMEM_SZ>>>(
        hT0, hT1, wk0, wk1, nullptr, kT0, kT1,
        Cn, Cn, Cn, Cn, CT, 0, CT, k_b, nullptr, 0, 1.f);

    // 5: V projection -> vv [C,T] hi/lo
    dim3 gV(Tn / 128, Cn / 128, Bn);
    tgemm<1, false, true><<<gV, 256, SMEM_SZ>>>(
        wv0, wv1, hT0, hT1, nullptr, vv0, vv1,
        Cn, Cn, Cn, Tn, 0, CT, CT, v_b, nullptr, 0, 1.f);

    // 6: Scores -> s fp32
    dim3 gS(Tn / 128, Tn / 128, Bn);
    tgemm<0, false, false><<<gS, 256, SMEM_SZ>>>(
        qT0, qT1, kT0, kT1, s, nullptr, nullptr,
        Cn, Cn, Cn, Tn, CT, CT, TT, nullptr, nullptr, 0,
        1.f / sqrtf((float)Cn));

    // 7: Softmax rows -> wt hi/lo
    softmax_split<<<Bn * Tn, 256>>>();

    // 8: Attn*V -> aT hi/lo
    dim3 gA(Cn / 128, Tn / 128, Bn);
    tgemm<0, false, true><<<gA, 256, SMEM_SZ>>>(
        wt0, wt1, vv0, vv1, nullptr, aT0, aT1,
        Tn, Tn, Tn, Cn, TT, CT, CT, nullptr, nullptr, 0, 1.f);

    // 9: Out proj + bias + residual -> out fp32
    dim3 gO(Tn / 128, Cn / 128, Bn);
    tgemm<1, true, false><<<gO, 256, SMEM_SZ>>>(
        wo0, wo1, aT0, aT1, out, nullptr, nullptr,
        Cn, Cn, Cn, Tn, 0, CT, CT, o_b, x, CT, 1.f);
}

// round 7
// speedup vs baseline: 3.0385x; 1.0239x over previous
#include <cuda_runtime.h>
#include <cuda_bf16.h>
#include <math.h>
#include <stdint.h>

#define Bn 8
#define Cn 512
#define Tn 2048
#define CT ((size_t)Cn * Tn)
#define TT ((size_t)Tn * Tn)
#define QKC 1024                         // stacked q|k channel dim
#define QKT ((size_t)Tn * QKC)           // per-batch qk plane

typedef __nv_bfloat16 bf16;

// ---------------- scratch (static device globals; allocation-guard safe) ----
// Flat [2][plane] arrays: index 0 = hi half, 1 = lo half. Host resolves the
// BASE symbol only (cudaGetSymbolAddress on an interior offset fails).
__device__ __align__(16) bf16 g_hT[2][Bn * Tn * Cn];    // [B,T,C] hi/lo
__device__ __align__(16) bf16 g_wqk[2][QKC * Cn];       // [Wq;Wk] stacked
__device__ __align__(16) bf16 g_wv[2][Cn * Cn];
__device__ __align__(16) bf16 g_wo[2][Cn * Cn];
__device__ __align__(16) float g_qkb[QKC];              // [q_b;k_b]
__device__ __align__(16) bf16 g_qk[2][Bn * Tn * QKC];   // [B,T,1024] q|k
__device__ __align__(16) bf16 g_vv[2][Bn * Cn * Tn];    // [B,C,T]
__device__ __align__(16) bf16 g_aT[2][Bn * Tn * Cn];    // [B,T,C]
__device__ __align__(16) float g_s[Bn * Tn * Tn];       // scores fp32 (134MB)
__device__ __align__(16) bf16 g_wt[2][Bn * Tn * Tn];    // softmax weights hi/lo
__device__ __align__(16) float g_mean[Bn * 32];
__device__ __align__(16) float g_inv[Bn * 32];

// ---------------- PTX helpers ----------------------------------------------
__device__ __forceinline__ uint32_t s2u(const void* p) {
    uint32_t a;
    asm("{ .reg .u64 t; cvta.to.shared.u64 t, %1; cvt.u32.u64 %0, t; }"
        : "=r"(a) : "l"(p));
    return a;
}

__device__ __forceinline__ void cp16(uint32_t d, const void* s) {
    asm volatile("cp.async.cg.shared.global [%0], [%1], 16;" :: "r"(d), "l"(s) : "memory");
}

#define LDSM4(r, addr)                                                          \
    asm volatile("ldmatrix.sync.aligned.m8n8.x4.shared.b16 {%0,%1,%2,%3}, [%4];"\
        : "=r"((r)[0]), "=r"((r)[1]), "=r"((r)[2]), "=r"((r)[3]) : "r"(addr))

#define MMA16816(d, a, b0, b1)                                                  \
    asm volatile(                                                               \
        "mma.sync.aligned.m16n8k16.row.col.f32.bf16.bf16.f32 "                  \
        "{%0,%1,%2,%3}, {%4,%5,%6,%7}, {%8,%9}, {%0,%1,%2,%3};"                 \
        : "+f"((d)[0]), "+f"((d)[1]), "+f"((d)[2]), "+f"((d)[3])                \
        : "r"((a)[0]), "r"((a)[1]), "r"((a)[2]), "r"((a)[3]),                   \
          "r"(b0), "r"(b1))

// ---------------- GroupNorm stats -------------------------------------------
__global__ void gn_stats(const float* __restrict__ x) {
    const int bg = blockIdx.x, tid = threadIdx.x;
    const int b = bg >> 5, g = bg & 31;
    const size_t base = ((size_t)b * Cn + g * 16) * Tn;
    const float4* xv = (const float4*)(x + base);
    float s = 0.f, ss = 0.f;
    for (int i = tid; i < 8192; i += 256) {
        float4 v = xv[i];
        s += v.x + v.y + v.z + v.w;
        ss += v.x * v.x + v.y * v.y + v.z * v.z + v.w * v.w;
    }
    __shared__ float rs[256], rq[256];
    rs[tid] = s; rq[tid] = ss;
    __syncthreads();
    for (int o = 128; o > 0; o >>= 1) {
        if (tid < o) { rs[tid] += rs[tid + o]; rq[tid] += rq[tid + o]; }
        __syncthreads();
    }
    if (tid == 0) {
        float mean = rs[0] / 32768.f;
        float var = rq[0] / 32768.f - mean * mean;
        g_mean[bg] = mean;
        g_inv[bg] = rsqrtf(var + 1e-6f);
    }
}

// ---------------- GN apply + transpose + bf16 split:  x[C,T] -> hT[T,C] -----
__global__ void hsplit(const float* __restrict__ x, const float* __restrict__ gamma,
                       const float* __restrict__ beta) {
    __shared__ float tl[32][33];
    const int b = blockIdx.z, t0 = blockIdx.x * 32, c0 = blockIdx.y * 32;
    const int tx = threadIdx.x, ty = threadIdx.y;
#pragma unroll
    for (int k = 0; k < 4; k++) {
        int c = c0 + ty + k * 8;
        float ga = gamma[c] * g_inv[b * 32 + (c >> 4)];
        float be = beta[c] - g_mean[b * 32 + (c >> 4)] * ga;
        float v = x[((size_t)b * Cn + c) * Tn + t0 + tx];
        tl[ty + k * 8][tx] = v * ga + be;
    }
    __syncthreads();
#pragma unroll
    for (int k = 0; k < 4; k++) {
        int t = t0 + ty + k * 8;
        float v = tl[tx][ty + k * 8];
        bf16 h = __float2bfloat16(v);
        size_t o = ((size_t)b * Tn + t) * Cn + c0 + tx;
        g_hT[0][o] = h;
        g_hT[1][o] = __float2bfloat16(v - __bfloat162float(h));
    }
}

// ------- weights -> bf16 hi/lo (Wq|Wk stacked) + qk bias concat, one launch --
__global__ void wsplit(const float* __restrict__ qw, const float* __restrict__ kw,
                       const float* __restrict__ vw, const float* __restrict__ ow,
                       const float* __restrict__ qb, const float* __restrict__ kb) {
    const int n = Cn * Cn;
    int i = blockIdx.x * blockDim.x + threadIdx.x;
    if (i < QKC) g_qkb[i] = (i < Cn) ? qb[i] : kb[i - Cn];
    if (i >= 4 * n) return;
    int seg = i / n, j = i - seg * n;
    const float* src = (seg == 0) ? qw : (seg == 1) ? kw : (seg == 2) ? vw : ow;
    float v = src[j];
    bf16 h = __float2bfloat16(v);
    bf16 l = __float2bfloat16(v - __bfloat162float(h));
    bf16* hd;
    bf16* ld;
    if (seg == 0)      { hd = g_wqk[0];     ld = g_wqk[1]; }
    else if (seg == 1) { hd = g_wqk[0] + n; ld = g_wqk[1] + n; }
    else if (seg == 2) { hd = g_wv[0];      ld = g_wv[1]; }
    else               { hd = g_wo[0];      ld = g_wo[1]; }
    hd[j] = h;
    ld[j] = l;
}

// ---------------- row softmax + bf16 hi/lo split ----------------------------
__global__ void softmax_split() {
    const size_t ro = (size_t)blockIdx.x * Tn;
    const float4* pv = (const float4*)(g_s + ro);
    const int tid = threadIdx.x;
    float4 v0 = pv[tid], v1 = pv[tid + 256];
    float mx = fmaxf(fmaxf(fmaxf(v0.x, v0.y), fmaxf(v0.z, v0.w)),
                     fmaxf(fmaxf(v1.x, v1.y), fmaxf(v1.z, v1.w)));
    __shared__ float red[256];
    red[tid] = mx;
    __syncthreads();
    for (int o = 128; o > 0; o >>= 1) {
        if (tid < o) red[tid] = fmaxf(red[tid], red[tid + o]);
        __syncthreads();
    }
    mx = red[0];
    __syncthreads();
    v0.x = __expf(v0.x - mx); v0.y = __expf(v0.y - mx);
    v0.z = __expf(v0.z - mx); v0.w = __expf(v0.w - mx);
    v1.x = __expf(v1.x - mx); v1.y = __expf(v1.y - mx);
    v1.z = __expf(v1.z - mx); v1.w = __expf(v1.w - mx);
    red[tid] = v0.x + v0.y + v0.z + v0.w + v1.x + v1.y + v1.z + v1.w;
    __syncthreads();
    for (int o = 128; o > 0; o >>= 1) {
        if (tid < o) red[tid] += red[tid + o];
        __syncthreads();
    }
    const float inv = 1.f / red[0];
    float a0[4] = {v0.x * inv, v0.y * inv, v0.z * inv, v0.w * inv};
    float a1[4] = {v1.x * inv, v1.y * inv, v1.z * inv, v1.w * inv};
    __align__(8) bf16 h[4], l[4];
#pragma unroll
    for (int i = 0; i < 4; i++) {
        h[i] = __float2bfloat16(a0[i]);
        l[i] = __float2bfloat16(a0[i] - __bfloat162float(h[i]));
    }
    *(uint2*)(g_wt[0] + ro + 4 * tid) = *(uint2*)h;
    *(uint2*)(g_wt[1] + ro + 4 * tid) = *(uint2*)l;
#pragma unroll
    for (int i = 0; i < 4; i++) {
        h[i] = __float2bfloat16(a1[i]);
        l[i] = __float2bfloat16(a1[i] - __bfloat162float(h[i]));
    }
    *(uint2*)(g_wt[0] + ro + 1024 + 4 * tid) = *(uint2*)h;
    *(uint2*)(g_wt[1] + ro + 1024 + 4 * tid) = *(uint2*)l;
}

// ---------------- mma.sync split-bf16 GEMM, 3-stage pipeline ----------------
// D[m,n] = scale * sum over 3 segs of A_seg[m,k]*B_seg[n,k]  (+bias +res)
// segs: (Ahi,Bhi), (Ahi,Blo), (Alo,Bhi) — exact-split fp32 emulation.
// CTA tile 128x128, BK=64, 8 warps (2m x 4n), warp tile 64x32.
// Both operands K-major; SMEM rows 128B with XOR-16B swizzle.
#define STG_A 16384
#define STG_AB 32768
#define NSTAGE 3
#define SMEM_SZ (NSTAGE * STG_AB)   // 98304

template <int BIAS_MODE, bool HAS_RES, bool OUT_SPLIT>
__global__ __launch_bounds__(256, 2) void tgemm(
    const bf16* __restrict__ Ahi, const bf16* __restrict__ Alo,
    const bf16* __restrict__ Bhi, const bf16* __restrict__ Blo,
    float* __restrict__ Cf, bf16* __restrict__ Ohi, bf16* __restrict__ Olo,
    int K, int lda, int ldb, int ldc,
    size_t sA, size_t sB, size_t sC,
    const float* __restrict__ bias, const float* __restrict__ res, size_t sRes,
    float scale) {
    extern __shared__ char smem[];
    const uint32_t sb = s2u(smem);
    const int tid = threadIdx.x, wid = tid >> 5, lane = tid & 31;
    const int m0 = blockIdx.y * 128, n0 = blockIdx.x * 128, b = blockIdx.z;
    const int wm = (wid >> 2) * 64, wn = (wid & 3) * 32;

    const char* As[3];
    const char* Bs[3];
    As[0] = (const char*)(Ahi + (size_t)b * sA + (size_t)m0 * lda);
    As[1] = As[0];
    As[2] = (const char*)(Alo + (size_t)b * sA + (size_t)m0 * lda);
    Bs[0] = (const char*)(Bhi + (size_t)b * sB + (size_t)n0 * ldb);
    Bs[1] = (const char*)(Blo + (size_t)b * sB + (size_t)n0 * ldb);
    Bs[2] = Bs[0];

    const int KS = K >> 6, S = 3 * KS;
    const size_t la2 = (size_t)lda * 2, lb2 = (size_t)ldb * 2;

    auto load = [&](int s, int buf) {
        int seg = (s >= KS) + (s >= 2 * KS);
        size_t kb = (size_t)((s - seg * KS) << 7);  // k0*2 bytes
        const char* Ap = As[seg] + kb;
        const char* Bp = Bs[seg] + kb;
        uint32_t ab = sb + buf * STG_AB;
        uint32_t bb = ab + STG_A;
#pragma unroll
        for (int j = 0; j < 4; j++) {
            int g = tid + j * 256;
            int r = g >> 3, c = g & 7;
            uint32_t sw = (uint32_t)(r * 128 + ((c ^ (r & 7)) << 4));
            cp16(ab + sw, Ap + (size_t)r * la2 + c * 16);
            cp16(bb + sw, Bp + (size_t)r * lb2 + c * 16);
        }
    };

    float acc[4][4][4];
#pragma unroll
    for (int i = 0; i < 4; i++)
#pragma unroll
        for (int j = 0; j < 4; j++)
#pragma unroll
            for (int q = 0; q < 4; q++) acc[i][j][q] = 0.f;

    // prologue: two stages in flight
    load(0, 0);
    asm volatile("cp.async.commit_group;");
    load(1, 1);
    asm volatile("cp.async.commit_group;");

    int cur = 0;
    for (int s = 0; s < S; s++) {
        asm volatile("cp.async.wait_group 1;");  // all but newest group landed
        __syncthreads();
        if (s + 2 < S) load(s + 2, (cur + 2) % NSTAGE);
        asm volatile("cp.async.commit_group;");  // empty-group commits keep recency window exact
        const uint32_t ab = sb + cur * STG_AB;
        const uint32_t bb = ab + STG_A;
#pragma unroll
        for (int kk = 0; kk < 4; kk++) {
            uint32_t af[4][4], bfr[2][4];
#pragma unroll
            for (int mi = 0; mi < 4; mi++) {
                int r = wm + mi * 16 + (lane & 15);
                int c = kk * 2 + (lane >> 4);
                LDSM4(af[mi], ab + r * 128 + ((c ^ (r & 7)) << 4));
            }
#pragma unroll
            for (int nj = 0; nj < 2; nj++) {
                int r = wn + nj * 16 + (lane & 7) + ((lane >> 4) << 3);
                int c = kk * 2 + ((lane >> 3) & 1);
                LDSM4(bfr[nj], bb + r * 128 + ((c ^ (r & 7)) << 4));
            }
#pragma unroll
            for (int mi = 0; mi < 4; mi++)
#pragma unroll
                for (int nj = 0; nj < 2; nj++) {
                    MMA16816(acc[mi][nj * 2 + 0], af[mi], bfr[nj][0], bfr[nj][1]);
                    MMA16816(acc[mi][nj * 2 + 1], af[mi], bfr[nj][2], bfr[nj][3]);
                }
        }
        cur = (cur + 1 == NSTAGE) ? 0 : cur + 1;
    }

    // ---------------- epilogue (register accumulators -> global) -----------
    const int qr = lane >> 2, qc = (lane & 3) * 2;
#pragma unroll
    for (int mi = 0; mi < 4; mi++) {
#pragma unroll
        for (int ni = 0; ni < 4; ni++) {
            const int mA = m0 + wm + mi * 16 + qr;
            const int nA = n0 + wn + ni * 8 + qc;
#pragma unroll
            for (int h = 0; h < 2; h++) {
                const int m = mA + h * 8;
                float v0 = acc[mi][ni][h * 2 + 0] * scale;
                float v1 = acc[mi][ni][h * 2 + 1] * scale;
                if (BIAS_MODE == 1) { float bv = bias[m]; v0 += bv; v1 += bv; }
                if (BIAS_MODE == 2) { v0 += bias[nA]; v1 += bias[nA + 1]; }
                const size_t go = (size_t)m * ldc + nA;
                if (OUT_SPLIT) {
                    bf16 h0 = __float2bfloat16(v0);
                    bf16 h1 = __float2bfloat16(v1);
                    bf16 l0 = __float2bfloat16(v0 - __bfloat162float(h0));
                    bf16 l1 = __float2bfloat16(v1 - __bfloat162float(h1));
                    __align__(4) bf16 ph[2] = {h0, h1};
                    __align__(4) bf16 pl[2] = {l0, l1};
                    *(uint32_t*)(Ohi + (size_t)b * sC + go) = *(uint32_t*)ph;
                    *(uint32_t*)(Olo + (size_t)b * sC + go) = *(uint32_t*)pl;
                } else {
                    if (HAS_RES) {
                        float2 r2 = *(const float2*)(res + (size_t)b * sRes + go);
                        v0 += r2.x; v1 += r2.y;
                    }
                    float2 o2 = {v0, v1};
                    *(float2*)(Cf + (size_t)b * sC + go) = o2;
                }
            }
        }
    }
}

// ---------------- launch ----------------------------------------------------
// Resolve the BASE symbol only; interior offsets computed host-side.
template <typename T>
static T* sym_base(const void* sym) {
    void* p = nullptr;
    cudaGetSymbolAddress(&p, sym);
    return (T*)p;
}

extern "C" void kernel_launch(void* const* d_in, const int* in_sizes, int n_in,
                              void* d_out, int out_size) {
    const float* x = (const float*)d_in[0];
    const float* gamma = (const float*)d_in[1];
    const float* beta = (const float*)d_in[2];
    const float* q_w = (const float*)d_in[3];
    const float* q_b = (const float*)d_in[4];
    const float* k_w = (const float*)d_in[5];
    const float* k_b = (const float*)d_in[6];
    const float* v_w = (const float*)d_in[7];
    const float* v_b = (const float*)d_in[8];
    const float* o_w = (const float*)d_in[9];
    const float* o_b = (const float*)d_in[10];
    float* out = (float*)d_out;

    cudaFuncSetAttribute(tgemm<2, false, true>, cudaFuncAttributeMaxDynamicSharedMemorySize, SMEM_SZ);
    cudaFuncSetAttribute(tgemm<1, false, true>, cudaFuncAttributeMaxDynamicSharedMemorySize, SMEM_SZ);
    cudaFuncSetAttribute(tgemm<0, false, false>, cudaFuncAttributeMaxDynamicSharedMemorySize, SMEM_SZ);
    cudaFuncSetAttribute(tgemm<0, false, true>, cudaFuncAttributeMaxDynamicSharedMemorySize, SMEM_SZ);
    cudaFuncSetAttribute(tgemm<1, true, false>, cudaFuncAttributeMaxDynamicSharedMemorySize, SMEM_SZ);

    const size_t PL  = (size_t)Bn * Tn * Cn;   // bf16 plane (activations)
    const size_t PQK = (size_t)Bn * Tn * QKC;  // bf16 plane (stacked q|k)
    const size_t PWQK = (size_t)QKC * Cn;      // stacked weight plane
    const size_t PW  = (size_t)Cn * Cn;
    const size_t PS  = (size_t)Bn * Tn * Tn;

    bf16* hT0 = sym_base<bf16>(g_hT);  bf16* hT1 = hT0 + PL;
    bf16* wqk0 = sym_base<bf16>(g_wqk); bf16* wqk1 = wqk0 + PWQK;
    bf16* wv0 = sym_base<bf16>(g_wv);  bf16* wv1 = wv0 + PW;
    bf16* wo0 = sym_base<bf16>(g_wo);  bf16* wo1 = wo0 + PW;
    bf16* qk0 = sym_base<bf16>(g_qk);  bf16* qk1 = qk0 + PQK;
    bf16* vv0 = sym_base<bf16>(g_vv);  bf16* vv1 = vv0 + PL;
    bf16* aT0 = sym_base<bf16>(g_aT);  bf16* aT1 = aT0 + PL;
    bf16* wt0 = sym_base<bf16>(g_wt);  bf16* wt1 = wt0 + PS;
    float* s = sym_base<float>(g_s);
    float* qkb = sym_base<float>(g_qkb);

    // 0: GN stats  1: GN apply+transpose+split  2: weights split + bias concat
    gn_stats<<<Bn * 32, 256>>>(x);
    hsplit<<<dim3(Tn / 32, Cn / 32, Bn), dim3(32, 8)>>>(x, gamma, beta);
    wsplit<<<(4 * Cn * Cn + 255) / 256, 256>>>(q_w, k_w, v_w, o_w, q_b, k_b);

    // 3: merged Q|K projection -> qk[B,T,1024] hi/lo
    dim3 gQK(QKC / 128, Tn / 128, Bn);   // 8 x 16 x 8 = 1024 CTAs
    tgemm<2, false, true><<<gQK, 256, SMEM_SZ>>>(
        hT0, hT1, wqk0, wqk1, nullptr, qk0, qk1,
        Cn, Cn, Cn, QKC, CT, 0, QKT, qkb, nullptr, 0, 1.f);

    // 4: V projection -> vv [C,T] hi/lo
    dim3 gV(Tn / 128, Cn / 128, Bn);
    tgemm<1, false, true><<<gV, 256, SMEM_SZ>>>(
        wv0, wv1, hT0, hT1, nullptr, vv0, vv1,
        Cn, Cn, Cn, Tn, 0, CT, CT, v_b, nullptr, 0, 1.f);

    // 5: Scores -> s fp32   (ncu capture slot: the dominant kernel)
    dim3 gS(Tn / 128, Tn / 128, Bn);
    tgemm<0, false, false><<<gS, 256, SMEM_SZ>>>(
        qk0, qk1, qk0 + Cn, qk1 + Cn, s, nullptr, nullptr,
        Cn, QKC, QKC, Tn, QKT, QKT, TT, nullptr, nullptr, 0,
        1.f / sqrtf((float)Cn));

    // 6: Softmax rows -> wt hi/lo
    softmax_split<<<Bn * Tn, 256>>>();

    // 7: Attn*V -> aT hi/lo
    dim3 gA(Cn / 128, Tn / 128, Bn);
    tgemm<0, false, true><<<gA, 256, SMEM_SZ>>>(
        wt0, wt1, vv0, vv1, nullptr, aT0, aT1,
        Tn, Tn, Tn, Cn, TT, CT, CT, nullptr, nullptr, 0, 1.f);

    // 8: Out proj + bias + residual -> out fp32
    dim3 gO(Tn / 128, Cn / 128, Bn);
    tgemm<1, true, false><<<gO, 256, SMEM_SZ>>>(
        wo0, wo1, aT0, aT1, out, nullptr, nullptr,
        Cn, Cn, Cn, Tn, 0, CT, CT, o_b, x, CT, 1.f);
}

// round 8
// speedup vs baseline: 4.2824x; 1.4094x over previous
#include <cuda_runtime.h>
#include <cuda_fp16.h>
#include <math.h>
#include <stdint.h>

#define Bn 8
#define Cn 512
#define Tn 2048
#define CT ((size_t)Cn * Tn)
#define TT ((size_t)Tn * Tn)
#define QKC 1024                         // stacked q|k channel dim
#define QKT ((size_t)Tn * QKC)           // per-batch qk plane

typedef __half fp16;

// ---------------- scratch (static device globals; allocation-guard safe) ----
// [2][plane]: 0 = fp16 hi, 1 = fp16 lo (exact split, A operands).
// B-only tensors are single-plane (rounded fp16).
__device__ __align__(16) fp16 g_hT[2][Bn * Tn * Cn];    // [B,T,C] hi/lo (A + B.hi)
__device__ __align__(16) fp16 g_wqk[QKC * Cn];          // [Wq;Wk] rounded (B only)
__device__ __align__(16) fp16 g_wv[2][Cn * Cn];         // A of V-proj
__device__ __align__(16) fp16 g_wo[2][Cn * Cn];         // A of out-proj
__device__ __align__(16) float g_qkb[QKC];              // [q_b;k_b]
__device__ __align__(16) fp16 g_qk[2][Bn * Tn * QKC];   // q|k: q=A split, k=B (hi)
__device__ __align__(16) fp16 g_vv[Bn * Cn * Tn];       // [B,C,T] rounded (B only)
__device__ __align__(16) fp16 g_aT[Bn * Tn * Cn];       // [B,T,C] rounded (B only)
__device__ __align__(16) float g_s[Bn * Tn * Tn];       // scores fp32 (134MB)
__device__ __align__(16) fp16 g_wt[2][Bn * Tn * Tn];    // softmax weights hi/lo (A)
__device__ __align__(16) float g_mean[Bn * 32];
__device__ __align__(16) float g_inv[Bn * 32];

// ---------------- PTX helpers ----------------------------------------------
__device__ __forceinline__ uint32_t s2u(const void* p) {
    uint32_t a;
    asm("{ .reg .u64 t; cvta.to.shared.u64 t, %1; cvt.u32.u64 %0, t; }"
        : "=r"(a) : "l"(p));
    return a;
}

__device__ __forceinline__ void cp16(uint32_t d, const void* s) {
    asm volatile("cp.async.cg.shared.global [%0], [%1], 16;" :: "r"(d), "l"(s) : "memory");
}

#define LDSM4(r, addr)                                                          \
    asm volatile("ldmatrix.sync.aligned.m8n8.x4.shared.b16 {%0,%1,%2,%3}, [%4];"\
        : "=r"((r)[0]), "=r"((r)[1]), "=r"((r)[2]), "=r"((r)[3]) : "r"(addr))

#define MMA16816(d, a, b0, b1)                                                  \
    asm volatile(                                                               \
        "mma.sync.aligned.m16n8k16.row.col.f32.f16.f16.f32 "                    \
        "{%0,%1,%2,%3}, {%4,%5,%6,%7}, {%8,%9}, {%0,%1,%2,%3};"                 \
        : "+f"((d)[0]), "+f"((d)[1]), "+f"((d)[2]), "+f"((d)[3])                \
        : "r"((a)[0]), "r"((a)[1]), "r"((a)[2]), "r"((a)[3]),                   \
          "r"(b0), "r"(b1))

__device__ __forceinline__ void hsplit2(float v, fp16& h, fp16& l) {
    h = __float2half_rn(v);
    l = __float2half_rn(v - __half2float(h));
}

// ---------------- GroupNorm stats -------------------------------------------
__global__ void gn_stats(const float* __restrict__ x) {
    const int bg = blockIdx.x, tid = threadIdx.x;
    const int b = bg >> 5, g = bg & 31;
    const size_t base = ((size_t)b * Cn + g * 16) * Tn;
    const float4* xv = (const float4*)(x + base);
    float s = 0.f, ss = 0.f;
    for (int i = tid; i < 8192; i += 256) {
        float4 v = xv[i];
        s += v.x + v.y + v.z + v.w;
        ss += v.x * v.x + v.y * v.y + v.z * v.z + v.w * v.w;
    }
    __shared__ float rs[256], rq[256];
    rs[tid] = s; rq[tid] = ss;
    __syncthreads();
    for (int o = 128; o > 0; o >>= 1) {
        if (tid < o) { rs[tid] += rs[tid + o]; rq[tid] += rq[tid + o]; }
        __syncthreads();
    }
    if (tid == 0) {
        float mean = rs[0] / 32768.f;
        float var = rq[0] / 32768.f - mean * mean;
        g_mean[bg] = mean;
        g_inv[bg] = rsqrtf(var + 1e-6f);
    }
}

// ---------------- GN apply + transpose + fp16 split:  x[C,T] -> hT[T,C] -----
__global__ void hsplit(const float* __restrict__ x, const float* __restrict__ gamma,
                       const float* __restrict__ beta) {
    __shared__ float tl[32][33];
    const int b = blockIdx.z, t0 = blockIdx.x * 32, c0 = blockIdx.y * 32;
    const int tx = threadIdx.x, ty = threadIdx.y;
#pragma unroll
    for (int k = 0; k < 4; k++) {
        int c = c0 + ty + k * 8;
        float ga = gamma[c] * g_inv[b * 32 + (c >> 4)];
        float be = beta[c] - g_mean[b * 32 + (c >> 4)] * ga;
        float v = x[((size_t)b * Cn + c) * Tn + t0 + tx];
        tl[ty + k * 8][tx] = v * ga + be;
    }
    __syncthreads();
#pragma unroll
    for (int k = 0; k < 4; k++) {
        int t = t0 + ty + k * 8;
        float v = tl[tx][ty + k * 8];
        fp16 h, l;
        hsplit2(v, h, l);
        size_t o = ((size_t)b * Tn + t) * Cn + c0 + tx;
        g_hT[0][o] = h;
        g_hT[1][o] = l;
    }
}

// ------- weights -> fp16 (Wq|Wk rounded; Wv/Wo split) + qk bias concat ------
__global__ void wsplit(const float* __restrict__ qw, const float* __restrict__ kw,
                       const float* __restrict__ vw, const float* __restrict__ ow,
                       const float* __restrict__ qb, const float* __restrict__ kb) {
    const int n = Cn * Cn;
    int i = blockIdx.x * blockDim.x + threadIdx.x;
    if (i < QKC) g_qkb[i] = (i < Cn) ? qb[i] : kb[i - Cn];
    if (i >= 4 * n) return;
    int seg = i / n, j = i - seg * n;
    if (seg == 0) { g_wqk[j] = __float2half_rn(qw[j]); return; }
    if (seg == 1) { g_wqk[n + j] = __float2half_rn(kw[j]); return; }
    const float v = (seg == 2) ? vw[j] : ow[j];
    fp16 h, l;
    hsplit2(v, h, l);
    if (seg == 2) { g_wv[0][j] = h; g_wv[1][j] = l; }
    else          { g_wo[0][j] = h; g_wo[1][j] = l; }
}

// ---------------- row softmax + fp16 hi/lo split ----------------------------
__global__ void softmax_split() {
    const size_t ro = (size_t)blockIdx.x * Tn;
    const float4* pv = (const float4*)(g_s + ro);
    const int tid = threadIdx.x;
    float4 v0 = pv[tid], v1 = pv[tid + 256];
    float mx = fmaxf(fmaxf(fmaxf(v0.x, v0.y), fmaxf(v0.z, v0.w)),
                     fmaxf(fmaxf(v1.x, v1.y), fmaxf(v1.z, v1.w)));
    __shared__ float red[256];
    red[tid] = mx;
    __syncthreads();
    for (int o = 128; o > 0; o >>= 1) {
        if (tid < o) red[tid] = fmaxf(red[tid], red[tid + o]);
        __syncthreads();
    }
    mx = red[0];
    __syncthreads();
    v0.x = __expf(v0.x - mx); v0.y = __expf(v0.y - mx);
    v0.z = __expf(v0.z - mx); v0.w = __expf(v0.w - mx);
    v1.x = __expf(v1.x - mx); v1.y = __expf(v1.y - mx);
    v1.z = __expf(v1.z - mx); v1.w = __expf(v1.w - mx);
    red[tid] = v0.x + v0.y + v0.z + v0.w + v1.x + v1.y + v1.z + v1.w;
    __syncthreads();
    for (int o = 128; o > 0; o >>= 1) {
        if (tid < o) red[tid] += red[tid + o];
        __syncthreads();
    }
    const float inv = 1.f / red[0];
    float a0[4] = {v0.x * inv, v0.y * inv, v0.z * inv, v0.w * inv};
    float a1[4] = {v1.x * inv, v1.y * inv, v1.z * inv, v1.w * inv};
    __align__(8) fp16 h[4], l[4];
#pragma unroll
    for (int i = 0; i < 4; i++) hsplit2(a0[i], h[i], l[i]);
    *(uint2*)(g_wt[0] + ro + 4 * tid) = *(uint2*)h;
    *(uint2*)(g_wt[1] + ro + 4 * tid) = *(uint2*)l;
#pragma unroll
    for (int i = 0; i < 4; i++) hsplit2(a1[i], h[i], l[i]);
    *(uint2*)(g_wt[0] + ro + 1024 + 4 * tid) = *(uint2*)h;
    *(uint2*)(g_wt[1] + ro + 1024 + 4 * tid) = *(uint2*)l;
}

// ---------------- mma.sync 2-pass split-fp16 GEMM, 3-stage pipeline ---------
// D[m,n] = scale * (Ahi + Alo)[m,k] * B[n,k]   (+bias +res)
// A split exactly into fp16 hi/lo (2 passes); B rounded once to fp16.
// CTA tile 128x128, BK=64, 8 warps (2m x 4n), warp tile 64x32.
// Both operands K-major; SMEM rows 128B with XOR-16B swizzle.
// OUT_MODE: 0 = fp32 (+opt residual), 1 = fp16 hi/lo split, 2 = fp16 single.
#define STG_A 16384
#define STG_AB 32768
#define NSTAGE 3
#define SMEM_SZ (NSTAGE * STG_AB)   // 98304

template <int BIAS_MODE, bool HAS_RES, int OUT_MODE>
__global__ __launch_bounds__(256, 2) void tgemm(
    const fp16* __restrict__ Ahi, const fp16* __restrict__ Alo,
    const fp16* __restrict__ Bh,
    float* __restrict__ Cf, fp16* __restrict__ Ohi, fp16* __restrict__ Olo,
    int K, int lda, int ldb, int ldc,
    size_t sA, size_t sB, size_t sC,
    const float* __restrict__ bias, const float* __restrict__ res, size_t sRes,
    float scale) {
    extern __shared__ char smem[];
    const uint32_t sb = s2u(smem);
    const int tid = threadIdx.x, wid = tid >> 5, lane = tid & 31;
    const int m0 = blockIdx.y * 128, n0 = blockIdx.x * 128, b = blockIdx.z;
    const int wm = (wid >> 2) * 64, wn = (wid & 3) * 32;

    const char* As[2];
    As[0] = (const char*)(Ahi + (size_t)b * sA + (size_t)m0 * lda);
    As[1] = (const char*)(Alo + (size_t)b * sA + (size_t)m0 * lda);
    const char* Bp0 = (const char*)(Bh + (size_t)b * sB + (size_t)n0 * ldb);

    const int KS = K >> 6, S = 2 * KS;
    const size_t la2 = (size_t)lda * 2, lb2 = (size_t)ldb * 2;

    auto load = [&](int s, int buf) {
        int seg = (s >= KS);
        size_t kb = (size_t)((s - seg * KS) << 7);  // k0*2 bytes
        const char* Ap = As[seg] + kb;
        const char* Bp = Bp0 + kb;
        uint32_t ab = sb + buf * STG_AB;
        uint32_t bb = ab + STG_A;
#pragma unroll
        for (int j = 0; j < 4; j++) {
            int g = tid + j * 256;
            int r = g >> 3, c = g & 7;
            uint32_t sw = (uint32_t)(r * 128 + ((c ^ (r & 7)) << 4));
            cp16(ab + sw, Ap + (size_t)r * la2 + c * 16);
            cp16(bb + sw, Bp + (size_t)r * lb2 + c * 16);
        }
    };

    float acc[4][4][4];
#pragma unroll
    for (int i = 0; i < 4; i++)
#pragma unroll
        for (int j = 0; j < 4; j++)
#pragma unroll
            for (int q = 0; q < 4; q++) acc[i][j][q] = 0.f;

    // prologue: two stages in flight
    load(0, 0);
    asm volatile("cp.async.commit_group;");
    load(1, 1);
    asm volatile("cp.async.commit_group;");

    int cur = 0;
    for (int s = 0; s < S; s++) {
        asm volatile("cp.async.wait_group 1;");  // all but newest group landed
        __syncthreads();
        if (s + 2 < S) load(s + 2, (cur + 2) % NSTAGE);
        asm volatile("cp.async.commit_group;");  // empty commits keep window exact
        const uint32_t ab = sb + cur * STG_AB;
        const uint32_t bb = ab + STG_A;
#pragma unroll
        for (int kk = 0; kk < 4; kk++) {
            uint32_t af[4][4], bfr[2][4];
#pragma unroll
            for (int mi = 0; mi < 4; mi++) {
                int r = wm + mi * 16 + (lane & 15);
                int c = kk * 2 + (lane >> 4);
                LDSM4(af[mi], ab + r * 128 + ((c ^ (r & 7)) << 4));
            }
#pragma unroll
            for (int nj = 0; nj < 2; nj++) {
                int r = wn + nj * 16 + (lane & 7) + ((lane >> 4) << 3);
                int c = kk * 2 + ((lane >> 3) & 1);
                LDSM4(bfr[nj], bb + r * 128 + ((c ^ (r & 7)) << 4));
            }
#pragma unroll
            for (int mi = 0; mi < 4; mi++)
#pragma unroll
                for (int nj = 0; nj < 2; nj++) {
                    MMA16816(acc[mi][nj * 2 + 0], af[mi], bfr[nj][0], bfr[nj][1]);
                    MMA16816(acc[mi][nj * 2 + 1], af[mi], bfr[nj][2], bfr[nj][3]);
                }
        }
        cur = (cur + 1 == NSTAGE) ? 0 : cur + 1;
    }

    // ---------------- epilogue (register accumulators -> global) -----------
    const int qr = lane >> 2, qc = (lane & 3) * 2;
#pragma unroll
    for (int mi = 0; mi < 4; mi++) {
#pragma unroll
        for (int ni = 0; ni < 4; ni++) {
            const int mA = m0 + wm + mi * 16 + qr;
            const int nA = n0 + wn + ni * 8 + qc;
#pragma unroll
            for (int h = 0; h < 2; h++) {
                const int m = mA + h * 8;
                float v0 = acc[mi][ni][h * 2 + 0] * scale;
                float v1 = acc[mi][ni][h * 2 + 1] * scale;
                if (BIAS_MODE == 1) { float bv = bias[m]; v0 += bv; v1 += bv; }
                if (BIAS_MODE == 2) { v0 += bias[nA]; v1 += bias[nA + 1]; }
                const size_t go = (size_t)m * ldc + nA;
                if (OUT_MODE == 1) {
                    fp16 h0, l0, h1, l1;
                    hsplit2(v0, h0, l0);
                    hsplit2(v1, h1, l1);
                    __align__(4) fp16 ph[2] = {h0, h1};
                    __align__(4) fp16 pl[2] = {l0, l1};
                    *(uint32_t*)(Ohi + (size_t)b * sC + go) = *(uint32_t*)ph;
                    *(uint32_t*)(Olo + (size_t)b * sC + go) = *(uint32_t*)pl;
                } else if (OUT_MODE == 2) {
                    __align__(4) fp16 ph[2] = {__float2half_rn(v0), __float2half_rn(v1)};
                    *(uint32_t*)(Ohi + (size_t)b * sC + go) = *(uint32_t*)ph;
                } else {
                    if (HAS_RES) {
                        float2 r2 = *(const float2*)(res + (size_t)b * sRes + go);
                        v0 += r2.x; v1 += r2.y;
                    }
                    float2 o2 = {v0, v1};
                    *(float2*)(Cf + (size_t)b * sC + go) = o2;
                }
            }
        }
    }
}

// ---------------- launch ----------------------------------------------------
// Resolve the BASE symbol only; interior offsets computed host-side.
template <typename T>
static T* sym_base(const void* sym) {
    void* p = nullptr;
    cudaGetSymbolAddress(&p, sym);
    return (T*)p;
}

extern "C" void kernel_launch(void* const* d_in, const int* in_sizes, int n_in,
                              void* d_out, int out_size) {
    const float* x = (const float*)d_in[0];
    const float* gamma = (const float*)d_in[1];
    const float* beta = (const float*)d_in[2];
    const float* q_w = (const float*)d_in[3];
    const float* q_b = (const float*)d_in[4];
    const float* k_w = (const float*)d_in[5];
    const float* k_b = (const float*)d_in[6];
    const float* v_w = (const float*)d_in[7];
    const float* v_b = (const float*)d_in[8];
    const float* o_w = (const float*)d_in[9];
    const float* o_b = (const float*)d_in[10];
    float* out = (float*)d_out;

    cudaFuncSetAttribute(tgemm<2, false, 1>, cudaFuncAttributeMaxDynamicSharedMemorySize, SMEM_SZ);
    cudaFuncSetAttribute(tgemm<1, false, 2>, cudaFuncAttributeMaxDynamicSharedMemorySize, SMEM_SZ);
    cudaFuncSetAttribute(tgemm<0, false, 0>, cudaFuncAttributeMaxDynamicSharedMemorySize, SMEM_SZ);
    cudaFuncSetAttribute(tgemm<0, false, 2>, cudaFuncAttributeMaxDynamicSharedMemorySize, SMEM_SZ);
    cudaFuncSetAttribute(tgemm<1, true, 0>, cudaFuncAttributeMaxDynamicSharedMemorySize, SMEM_SZ);

    const size_t PL  = (size_t)Bn * Tn * Cn;   // fp16 plane (activations)
    const size_t PQK = (size_t)Bn * Tn * QKC;  // fp16 plane (stacked q|k)
    const size_t PW  = (size_t)Cn * Cn;
    const size_t PS  = (size_t)Bn * Tn * Tn;

    fp16* hT0 = sym_base<fp16>(g_hT);  fp16* hT1 = hT0 + PL;
    fp16* wqk = sym_base<fp16>(g_wqk);
    fp16* wv0 = sym_base<fp16>(g_wv);  fp16* wv1 = wv0 + PW;
    fp16* wo0 = sym_base<fp16>(g_wo);  fp16* wo1 = wo0 + PW;
    fp16* qk0 = sym_base<fp16>(g_qk);  fp16* qk1 = qk0 + PQK;
    fp16* vv  = sym_base<fp16>(g_vv);
    fp16* aT  = sym_base<fp16>(g_aT);
    fp16* wt0 = sym_base<fp16>(g_wt);  fp16* wt1 = wt0 + PS;
    float* s = sym_base<float>(g_s);
    float* qkb = sym_base<float>(g_qkb);

    // 0: GN stats  1: GN apply+transpose+split  2: weights convert
    gn_stats<<<Bn * 32, 256>>>(x);
    hsplit<<<dim3(Tn / 32, Cn / 32, Bn), dim3(32, 8)>>>(x, gamma, beta);
    wsplit<<<(4 * Cn * Cn + 255) / 256, 256>>>(q_w, k_w, v_w, o_w, q_b, k_b);

    // 3: merged Q|K projection: A=hT split, B=Wqk rounded -> qk hi/lo
    dim3 gQK(QKC / 128, Tn / 128, Bn);
    tgemm<2, false, 1><<<gQK, 256, SMEM_SZ>>>(
        hT0, hT1, wqk, nullptr, qk0, qk1,
        Cn, Cn, Cn, QKC, CT, 0, QKT, qkb, nullptr, 0, 1.f);

    // 4: V projection: A=Wv split, B=hT rounded -> vv fp16 single
    dim3 gV(Tn / 128, Cn / 128, Bn);
    tgemm<1, false, 2><<<gV, 256, SMEM_SZ>>>(
        wv0, wv1, hT0, nullptr, vv, nullptr,
        Cn, Cn, Cn, Tn, 0, CT, CT, v_b, nullptr, 0, 1.f);

    // 5: Scores: A=q split, B=k rounded -> s fp32  (ncu capture slot)
    dim3 gS(Tn / 128, Tn / 128, Bn);
    tgemm<0, false, 0><<<gS, 256, SMEM_SZ>>>(
        qk0, qk1, qk0 + Cn, s, nullptr, nullptr,
        Cn, QKC, QKC, Tn, QKT, QKT, TT, nullptr, nullptr, 0,
        1.f / sqrtf((float)Cn));

    // 6: Softmax rows -> wt hi/lo
    softmax_split<<<Bn * Tn, 256>>>();

    // 7: Attn*V: A=wt split, B=vv rounded -> aT fp16 single
    dim3 gA(Cn / 128, Tn / 128, Bn);
    tgemm<0, false, 2><<<gA, 256, SMEM_SZ>>>(
        wt0, wt1, vv, nullptr, aT, nullptr,
        Tn, Tn, Tn, Cn, TT, CT, CT, nullptr, nullptr, 0, 1.f);

    // 8: Out proj: A=Wo split, B=aT rounded + bias + residual -> out fp32
    dim3 gO(Tn / 128, Cn / 128, Bn);
    tgemm<1, true, 0><<<gO, 256, SMEM_SZ>>>(
        wo0, wo1, aT, out, nullptr, nullptr,
        Cn, Cn, Cn, Tn, 0, CT, CT, o_b, x, CT, 1.f);
}

// round 9
// speedup vs baseline: 7.1987x; 1.6810x over previous
#include <cuda_runtime.h>
#include <cuda_fp16.h>
#include <math.h>
#include <stdint.h>

#define Bn 8
#define Cn 512
#define Tn 2048
#define CT ((size_t)Cn * Tn)
#define TT ((size_t)Tn * Tn)
#define QKC 1024                         // stacked q|k channel dim
#define QKT ((size_t)Tn * QKC)           // per-batch qk plane

typedef __half fp16;

// ---------------- scratch (static device globals; allocation-guard safe) ----
__device__ __align__(16) fp16 g_hT[Bn * Tn * Cn];    // [B,T,C] groupnormed, fp16
__device__ __align__(16) fp16 g_wqk[QKC * Cn];       // [Wq;Wk] fp16
__device__ __align__(16) fp16 g_wv[Cn * Cn];
__device__ __align__(16) fp16 g_wo[Cn * Cn];
__device__ __align__(16) float g_qkb[QKC];           // [q_b;k_b]
__device__ __align__(16) fp16 g_qk[Bn * Tn * QKC];   // [B,T,1024] q|k
__device__ __align__(16) fp16 g_vv[Bn * Cn * Tn];    // [B,C,T]
__device__ __align__(16) fp16 g_aT[Bn * Tn * Cn];    // [B,T,C]
__device__ __align__(16) float g_s[Bn * Tn * Tn];    // scores fp32 (134MB)
__device__ __align__(16) fp16 g_wt[Bn * Tn * Tn];    // softmax weights fp16
__device__ __align__(16) float g_mean[Bn * 32];
__device__ __align__(16) float g_inv[Bn * 32];

// ---------------- PTX helpers ----------------------------------------------
__device__ __forceinline__ uint32_t s2u(const void* p) {
    uint32_t a;
    asm("{ .reg .u64 t; cvta.to.shared.u64 t, %1; cvt.u32.u64 %0, t; }"
        : "=r"(a) : "l"(p));
    return a;
}

__device__ __forceinline__ void cp16(uint32_t d, const void* s) {
    asm volatile("cp.async.cg.shared.global [%0], [%1], 16;" :: "r"(d), "l"(s) : "memory");
}

#define LDSM4(r, addr)                                                          \
    asm volatile("ldmatrix.sync.aligned.m8n8.x4.shared.b16 {%0,%1,%2,%3}, [%4];"\
        : "=r"((r)[0]), "=r"((r)[1]), "=r"((r)[2]), "=r"((r)[3]) : "r"(addr))

#define MMA16816(d, a, b0, b1)                                                  \
    asm volatile(                                                               \
        "mma.sync.aligned.m16n8k16.row.col.f32.f16.f16.f32 "                    \
        "{%0,%1,%2,%3}, {%4,%5,%6,%7}, {%8,%9}, {%0,%1,%2,%3};"                 \
        : "+f"((d)[0]), "+f"((d)[1]), "+f"((d)[2]), "+f"((d)[3])                \
        : "r"((a)[0]), "r"((a)[1]), "r"((a)[2]), "r"((a)[3]),                   \
          "r"(b0), "r"(b1))

// ---------------- GroupNorm stats -------------------------------------------
__global__ void gn_stats(const float* __restrict__ x) {
    const int bg = blockIdx.x, tid = threadIdx.x;
    const int b = bg >> 5, g = bg & 31;
    const size_t base = ((size_t)b * Cn + g * 16) * Tn;
    const float4* xv = (const float4*)(x + base);
    float s = 0.f, ss = 0.f;
    for (int i = tid; i < 8192; i += 256) {
        float4 v = xv[i];
        s += v.x + v.y + v.z + v.w;
        ss += v.x * v.x + v.y * v.y + v.z * v.z + v.w * v.w;
    }
    __shared__ float rs[256], rq[256];
    rs[tid] = s; rq[tid] = ss;
    __syncthreads();
    for (int o = 128; o > 0; o >>= 1) {
        if (tid < o) { rs[tid] += rs[tid + o]; rq[tid] += rq[tid + o]; }
        __syncthreads();
    }
    if (tid == 0) {
        float mean = rs[0] / 32768.f;
        float var = rq[0] / 32768.f - mean * mean;
        g_mean[bg] = mean;
        g_inv[bg] = rsqrtf(var + 1e-6f);
    }
}

// ---------------- GN apply + transpose -> fp16:  x[C,T] -> hT[T,C] ----------
__global__ void happly(const float* __restrict__ x, const float* __restrict__ gamma,
                       const float* __restrict__ beta) {
    __shared__ float tl[32][33];
    const int b = blockIdx.z, t0 = blockIdx.x * 32, c0 = blockIdx.y * 32;
    const int tx = threadIdx.x, ty = threadIdx.y;
#pragma unroll
    for (int k = 0; k < 4; k++) {
        int c = c0 + ty + k * 8;
        float ga = gamma[c] * g_inv[b * 32 + (c >> 4)];
        float be = beta[c] - g_mean[b * 32 + (c >> 4)] * ga;
        float v = x[((size_t)b * Cn + c) * Tn + t0 + tx];
        tl[ty + k * 8][tx] = v * ga + be;
    }
    __syncthreads();
#pragma unroll
    for (int k = 0; k < 4; k++) {
        int t = t0 + ty + k * 8;
        size_t o = ((size_t)b * Tn + t) * Cn + c0 + tx;
        g_hT[o] = __float2half_rn(tl[tx][ty + k * 8]);
    }
}

// ------- weights -> fp16 + qk bias concat, one launch -----------------------
__global__ void wconv(const float* __restrict__ qw, const float* __restrict__ kw,
                      const float* __restrict__ vw, const float* __restrict__ ow,
                      const float* __restrict__ qb, const float* __restrict__ kb) {
    const int n = Cn * Cn;
    int i = blockIdx.x * blockDim.x + threadIdx.x;
    if (i < QKC) g_qkb[i] = (i < Cn) ? qb[i] : kb[i - Cn];
    if (i >= 4 * n) return;
    int seg = i / n, j = i - seg * n;
    if (seg == 0)      g_wqk[j]     = __float2half_rn(qw[j]);
    else if (seg == 1) g_wqk[n + j] = __float2half_rn(kw[j]);
    else if (seg == 2) g_wv[j]      = __float2half_rn(vw[j]);
    else               g_wo[j]      = __float2half_rn(ow[j]);
}

// ---------------- row softmax -> fp16 ---------------------------------------
__global__ void softmax_h() {
    const size_t ro = (size_t)blockIdx.x * Tn;
    const float4* pv = (const float4*)(g_s + ro);
    const int tid = threadIdx.x;
    float4 v0 = pv[tid], v1 = pv[tid + 256];
    float mx = fmaxf(fmaxf(fmaxf(v0.x, v0.y), fmaxf(v0.z, v0.w)),
                     fmaxf(fmaxf(v1.x, v1.y), fmaxf(v1.z, v1.w)));
    __shared__ float red[256];
    red[tid] = mx;
    __syncthreads();
    for (int o = 128; o > 0; o >>= 1) {
        if (tid < o) red[tid] = fmaxf(red[tid], red[tid + o]);
        __syncthreads();
    }
    mx = red[0];
    __syncthreads();
    v0.x = __expf(v0.x - mx); v0.y = __expf(v0.y - mx);
    v0.z = __expf(v0.z - mx); v0.w = __expf(v0.w - mx);
    v1.x = __expf(v1.x - mx); v1.y = __expf(v1.y - mx);
    v1.z = __expf(v1.z - mx); v1.w = __expf(v1.w - mx);
    red[tid] = v0.x + v0.y + v0.z + v0.w + v1.x + v1.y + v1.z + v1.w;
    __syncthreads();
    for (int o = 128; o > 0; o >>= 1) {
        if (tid < o) red[tid] += red[tid + o];
        __syncthreads();
    }
    const float inv = 1.f / red[0];
    __align__(8) fp16 h[4];
    h[0] = __float2half_rn(v0.x * inv); h[1] = __float2half_rn(v0.y * inv);
    h[2] = __float2half_rn(v0.z * inv); h[3] = __float2half_rn(v0.w * inv);
    *(uint2*)(g_wt + ro + 4 * tid) = *(uint2*)h;
    h[0] = __float2half_rn(v1.x * inv); h[1] = __float2half_rn(v1.y * inv);
    h[2] = __float2half_rn(v1.z * inv); h[3] = __float2half_rn(v1.w * inv);
    *(uint2*)(g_wt + ro + 1024 + 4 * tid) = *(uint2*)h;
}

// ---------------- mma.sync plain-fp16 GEMM, 3-stage pipeline ----------------
// D[m,n] = scale * A[m,k] * B[n,k]  (+bias +res)
// CTA tile 128x128, BK=64, 8 warps (2m x 4n), warp tile 64x32.
// Both operands K-major; SMEM rows 128B with XOR-16B swizzle.
// OUT_MODE: 0 = fp32 (+opt residual), 1 = fp16.
#define STG_A 16384
#define STG_AB 32768
#define NSTAGE 3
#define SMEM_SZ (NSTAGE * STG_AB)   // 98304

template <int BIAS_MODE, bool HAS_RES, int OUT_MODE>
__global__ __launch_bounds__(256, 2) void tgemm(
    const fp16* __restrict__ Ah, const fp16* __restrict__ Bh,
    float* __restrict__ Cf, fp16* __restrict__ Oh,
    int K, int lda, int ldb, int ldc,
    size_t sA, size_t sB, size_t sC,
    const float* __restrict__ bias, const float* __restrict__ res, size_t sRes,
    float scale) {
    extern __shared__ char smem[];
    const uint32_t sb = s2u(smem);
    const int tid = threadIdx.x, wid = tid >> 5, lane = tid & 31;
    const int m0 = blockIdx.y * 128, n0 = blockIdx.x * 128, b = blockIdx.z;
    const int wm = (wid >> 2) * 64, wn = (wid & 3) * 32;

    const char* Ap0 = (const char*)(Ah + (size_t)b * sA + (size_t)m0 * lda);
    const char* Bp0 = (const char*)(Bh + (size_t)b * sB + (size_t)n0 * ldb);

    const int S = K >> 6;
    const size_t la2 = (size_t)lda * 2, lb2 = (size_t)ldb * 2;

    auto load = [&](int s, int buf) {
        size_t kb = (size_t)s << 7;  // k0*2 bytes
        const char* Ap = Ap0 + kb;
        const char* Bp = Bp0 + kb;
        uint32_t ab = sb + buf * STG_AB;
        uint32_t bb = ab + STG_A;
#pragma unroll
        for (int j = 0; j < 4; j++) {
            int g = tid + j * 256;
            int r = g >> 3, c = g & 7;
            uint32_t sw = (uint32_t)(r * 128 + ((c ^ (r & 7)) << 4));
            cp16(ab + sw, Ap + (size_t)r * la2 + c * 16);
            cp16(bb + sw, Bp + (size_t)r * lb2 + c * 16);
        }
    };

    float acc[4][4][4];
#pragma unroll
    for (int i = 0; i < 4; i++)
#pragma unroll
        for (int j = 0; j < 4; j++)
#pragma unroll
            for (int q = 0; q < 4; q++) acc[i][j][q] = 0.f;

    // prologue: two stages in flight
    load(0, 0);
    asm volatile("cp.async.commit_group;");
    load(1, 1);
    asm volatile("cp.async.commit_group;");

    int cur = 0;
    for (int s = 0; s < S; s++) {
        asm volatile("cp.async.wait_group 1;");  // all but newest group landed
        __syncthreads();
        if (s + 2 < S) load(s + 2, (cur + 2) % NSTAGE);
        asm volatile("cp.async.commit_group;");  // empty commits keep window exact
        const uint32_t ab = sb + cur * STG_AB;
        const uint32_t bb = ab + STG_A;
#pragma unroll
        for (int kk = 0; kk < 4; kk++) {
            uint32_t af[4][4], bfr[2][4];
#pragma unroll
            for (int mi = 0; mi < 4; mi++) {
                int r = wm + mi * 16 + (lane & 15);
                int c = kk * 2 + (lane >> 4);
                LDSM4(af[mi], ab + r * 128 + ((c ^ (r & 7)) << 4));
            }
#pragma unroll
            for (int nj = 0; nj < 2; nj++) {
                int r = wn + nj * 16 + (lane & 7) + ((lane >> 4) << 3);
                int c = kk * 2 + ((lane >> 3) & 1);
                LDSM4(bfr[nj], bb + r * 128 + ((c ^ (r & 7)) << 4));
            }
#pragma unroll
            for (int mi = 0; mi < 4; mi++)
#pragma unroll
                for (int nj = 0; nj < 2; nj++) {
                    MMA16816(acc[mi][nj * 2 + 0], af[mi], bfr[nj][0], bfr[nj][1]);
                    MMA16816(acc[mi][nj * 2 + 1], af[mi], bfr[nj][2], bfr[nj][3]);
                }
        }
        cur = (cur + 1 == NSTAGE) ? 0 : cur + 1;
    }

    // ---------------- epilogue (register accumulators -> global) -----------
    const int qr = lane >> 2, qc = (lane & 3) * 2;
#pragma unroll
    for (int mi = 0; mi < 4; mi++) {
#pragma unroll
        for (int ni = 0; ni < 4; ni++) {
            const int mA = m0 + wm + mi * 16 + qr;
            const int nA = n0 + wn + ni * 8 + qc;
#pragma unroll
            for (int h = 0; h < 2; h++) {
                const int m = mA + h * 8;
                float v0 = acc[mi][ni][h * 2 + 0] * scale;
                float v1 = acc[mi][ni][h * 2 + 1] * scale;
                if (BIAS_MODE == 1) { float bv = bias[m]; v0 += bv; v1 += bv; }
                if (BIAS_MODE == 2) { v0 += bias[nA]; v1 += bias[nA + 1]; }
                const size_t go = (size_t)m * ldc + nA;
                if (OUT_MODE == 1) {
                    __align__(4) fp16 ph[2] = {__float2half_rn(v0), __float2half_rn(v1)};
                    *(uint32_t*)(Oh + (size_t)b * sC + go) = *(uint32_t*)ph;
                } else {
                    if (HAS_RES) {
                        float2 r2 = *(const float2*)(res + (size_t)b * sRes + go);
                        v0 += r2.x; v1 += r2.y;
                    }
                    float2 o2 = {v0, v1};
                    *(float2*)(Cf + (size_t)b * sC + go) = o2;
                }
            }
        }
    }
}

// ---------------- launch ----------------------------------------------------
// Resolve the BASE symbol only; interior offsets computed host-side.
template <typename T>
static T* sym_base(const void* sym) {
    void* p = nullptr;
    cudaGetSymbolAddress(&p, sym);
    return (T*)p;
}

extern "C" void kernel_launch(void* const* d_in, const int* in_sizes, int n_in,
                              void* d_out, int out_size) {
    const float* x = (const float*)d_in[0];
    const float* gamma = (const float*)d_in[1];
    const float* beta = (const float*)d_in[2];
    const float* q_w = (const float*)d_in[3];
    const float* q_b = (const float*)d_in[4];
    const float* k_w = (const float*)d_in[5];
    const float* k_b = (const float*)d_in[6];
    const float* v_w = (const float*)d_in[7];
    const float* v_b = (const float*)d_in[8];
    const float* o_w = (const float*)d_in[9];
    const float* o_b = (const float*)d_in[10];
    float* out = (float*)d_out;

    cudaFuncSetAttribute(tgemm<2, false, 1>, cudaFuncAttributeMaxDynamicSharedMemorySize, SMEM_SZ);
    cudaFuncSetAttribute(tgemm<1, false, 1>, cudaFuncAttributeMaxDynamicSharedMemorySize, SMEM_SZ);
    cudaFuncSetAttribute(tgemm<0, false, 0>, cudaFuncAttributeMaxDynamicSharedMemorySize, SMEM_SZ);
    cudaFuncSetAttribute(tgemm<0, false, 1>, cudaFuncAttributeMaxDynamicSharedMemorySize, SMEM_SZ);
    cudaFuncSetAttribute(tgemm<1, true, 0>, cudaFuncAttributeMaxDynamicSharedMemorySize, SMEM_SZ);

    fp16* hT = sym_base<fp16>(g_hT);
    fp16* wqk = sym_base<fp16>(g_wqk);
    fp16* wv = sym_base<fp16>(g_wv);
    fp16* wo = sym_base<fp16>(g_wo);
    fp16* qk = sym_base<fp16>(g_qk);
    fp16* vv = sym_base<fp16>(g_vv);
    fp16* aT = sym_base<fp16>(g_aT);
    fp16* wt = sym_base<fp16>(g_wt);
    float* s = sym_base<float>(g_s);
    float* qkb = sym_base<float>(g_qkb);

    // 0: GN stats  1: GN apply+transpose  2: weights convert
    gn_stats<<<Bn * 32, 256>>>(x);
    happly<<<dim3(Tn / 32, Cn / 32, Bn), dim3(32, 8)>>>(x, gamma, beta);
    wconv<<<(4 * Cn * Cn + 255) / 256, 256>>>(q_w, k_w, v_w, o_w, q_b, k_b);

    // 3: merged Q|K projection -> qk[B,T,1024] fp16
    dim3 gQK(QKC / 128, Tn / 128, Bn);
    tgemm<2, false, 1><<<gQK, 256, SMEM_SZ>>>(
        hT, wqk, nullptr, qk,
        Cn, Cn, Cn, QKC, CT, 0, QKT, qkb, nullptr, 0, 1.f);

    // 4: V projection -> vv [C,T] fp16
    dim3 gV(Tn / 128, Cn / 128, Bn);
    tgemm<1, false, 1><<<gV, 256, SMEM_SZ>>>(
        wv, hT, nullptr, vv,
        Cn, Cn, Cn, Tn, 0, CT, CT, v_b, nullptr, 0, 1.f);

    // 5: Scores -> s fp32  (ncu capture slot)
    dim3 gS(Tn / 128, Tn / 128, Bn);
    tgemm<0, false, 0><<<gS, 256, SMEM_SZ>>>(
        qk, qk + Cn, s, nullptr,
        Cn, QKC, QKC, Tn, QKT, QKT, TT, nullptr, nullptr, 0,
        1.f / sqrtf((float)Cn));

    // 6: Softmax rows -> wt fp16
    softmax_h<<<Bn * Tn, 256>>>();

    // 7: Attn*V -> aT fp16
    dim3 gA(Cn / 128, Tn / 128, Bn);
    tgemm<0, false, 1><<<gA, 256, SMEM_SZ>>>(
        wt, vv, nullptr, aT,
        Tn, Tn, Tn, Cn, TT, CT, CT, nullptr, nullptr, 0, 1.f);

    // 8: Out proj + bias + residual -> out fp32
    dim3 gO(Tn / 128, Cn / 128, Bn);
    tgemm<1, true, 0><<<gO, 256, SMEM_SZ>>>(
        wo, aT, out, nullptr,
        Cn, Cn, Cn, Tn, 0, CT, CT, o_b, x, CT, 1.f);
}

// round 10
// speedup vs baseline: 7.6983x; 1.0694x over previous
#include <cuda_runtime.h>
#include <cuda_fp16.h>
#include <math.h>
#include <stdint.h>

#define Bn 8
#define Cn 512
#define Tn 2048
#define CT ((size_t)Cn * Tn)
#define TT ((size_t)Tn * Tn)
#define QKC 1024                         // stacked q|k channel dim
#define QKT ((size_t)Tn * QKC)           // per-batch qk plane

typedef __half fp16;

// ---------------- scratch (static device globals; allocation-guard safe) ----
__device__ __align__(16) fp16 g_hT[Bn * Tn * Cn];    // [B,T,C] groupnormed, fp16
__device__ __align__(16) fp16 g_wqk[QKC * Cn];       // [Wq;Wk] fp16
__device__ __align__(16) fp16 g_wv[Cn * Cn];
__device__ __align__(16) fp16 g_wo[Cn * Cn];
__device__ __align__(16) float g_qkb[QKC];           // [q_b;k_b]
__device__ __align__(16) fp16 g_qk[Bn * Tn * QKC];   // [B,T,1024] q|k
__device__ __align__(16) fp16 g_vv[Bn * Cn * Tn];    // [B,C,T]
__device__ __align__(16) fp16 g_aT[Bn * Tn * Cn];    // [B,T,C]
__device__ __align__(16) fp16 g_wt[Bn * Tn * Tn];    // E = exp(scores), unnormalized
__device__ __align__(16) float g_zp[(size_t)Bn * Tn * 16];  // row-sum partials
__device__ __align__(16) float g_mean[Bn * 32];
__device__ __align__(16) float g_inv[Bn * 32];

// ---------------- PTX helpers ----------------------------------------------
__device__ __forceinline__ uint32_t s2u(const void* p) {
    uint32_t a;
    asm("{ .reg .u64 t; cvta.to.shared.u64 t, %1; cvt.u32.u64 %0, t; }"
        : "=r"(a) : "l"(p));
    return a;
}

__device__ __forceinline__ void cp16(uint32_t d, const void* s) {
    asm volatile("cp.async.cg.shared.global [%0], [%1], 16;" :: "r"(d), "l"(s) : "memory");
}

#define LDSM4(r, addr)                                                          \
    asm volatile("ldmatrix.sync.aligned.m8n8.x4.shared.b16 {%0,%1,%2,%3}, [%4];"\
        : "=r"((r)[0]), "=r"((r)[1]), "=r"((r)[2]), "=r"((r)[3]) : "r"(addr))

#define MMA16816(d, a, b0, b1)                                                  \
    asm volatile(                                                               \
        "mma.sync.aligned.m16n8k16.row.col.f32.f16.f16.f32 "                    \
        "{%0,%1,%2,%3}, {%4,%5,%6,%7}, {%8,%9}, {%0,%1,%2,%3};"                 \
        : "+f"((d)[0]), "+f"((d)[1]), "+f"((d)[2]), "+f"((d)[3])                \
        : "r"((a)[0]), "r"((a)[1]), "r"((a)[2]), "r"((a)[3]),                   \
          "r"(b0), "r"(b1))

// ---------------- GroupNorm stats -------------------------------------------
__global__ void gn_stats(const float* __restrict__ x) {
    const int bg = blockIdx.x, tid = threadIdx.x;
    const int b = bg >> 5, g = bg & 31;
    const size_t base = ((size_t)b * Cn + g * 16) * Tn;
    const float4* xv = (const float4*)(x + base);
    float s = 0.f, ss = 0.f;
    for (int i = tid; i < 8192; i += 256) {
        float4 v = xv[i];
        s += v.x + v.y + v.z + v.w;
        ss += v.x * v.x + v.y * v.y + v.z * v.z + v.w * v.w;
    }
    __shared__ float rs[256], rq[256];
    rs[tid] = s; rq[tid] = ss;
    __syncthreads();
    for (int o = 128; o > 0; o >>= 1) {
        if (tid < o) { rs[tid] += rs[tid + o]; rq[tid] += rq[tid + o]; }
        __syncthreads();
    }
    if (tid == 0) {
        float mean = rs[0] / 32768.f;
        float var = rq[0] / 32768.f - mean * mean;
        g_mean[bg] = mean;
        g_inv[bg] = rsqrtf(var + 1e-6f);
    }
}

// ---------------- GN apply + transpose -> fp16:  x[C,T] -> hT[T,C] ----------
__global__ void happly(const float* __restrict__ x, const float* __restrict__ gamma,
                       const float* __restrict__ beta) {
    __shared__ float tl[32][33];
    const int b = blockIdx.z, t0 = blockIdx.x * 32, c0 = blockIdx.y * 32;
    const int tx = threadIdx.x, ty = threadIdx.y;
#pragma unroll
    for (int k = 0; k < 4; k++) {
        int c = c0 + ty + k * 8;
        float ga = gamma[c] * g_inv[b * 32 + (c >> 4)];
        float be = beta[c] - g_mean[b * 32 + (c >> 4)] * ga;
        float v = x[((size_t)b * Cn + c) * Tn + t0 + tx];
        tl[ty + k * 8][tx] = v * ga + be;
    }
    __syncthreads();
#pragma unroll
    for (int k = 0; k < 4; k++) {
        int t = t0 + ty + k * 8;
        size_t o = ((size_t)b * Tn + t) * Cn + c0 + tx;
        g_hT[o] = __float2half_rn(tl[tx][ty + k * 8]);
    }
}

// ------- weights -> fp16 + qk bias concat, one launch -----------------------
__global__ void wconv(const float* __restrict__ qw, const float* __restrict__ kw,
                      const float* __restrict__ vw, const float* __restrict__ ow,
                      const float* __restrict__ qb, const float* __restrict__ kb) {
    const int n = Cn * Cn;
    int i = blockIdx.x * blockDim.x + threadIdx.x;
    if (i < QKC) g_qkb[i] = (i < Cn) ? qb[i] : kb[i - Cn];
    if (i >= 4 * n) return;
    int seg = i / n, j = i - seg * n;
    if (seg == 0)      g_wqk[j]     = __float2half_rn(qw[j]);
    else if (seg == 1) g_wqk[n + j] = __float2half_rn(kw[j]);
    else if (seg == 2) g_wv[j]      = __float2half_rn(vw[j]);
    else               g_wo[j]      = __float2half_rn(ow[j]);
}

// ---------------- mma.sync plain-fp16 GEMM, 3-stage pipeline ----------------
// D[m,n] = scale * A[m,k] * B[n,k]  (+bias +res)
// CTA tile 128x128, BK=64, 8 warps (2m x 4n), warp tile 64x32.
// Both operands K-major; SMEM rows 128B with XOR-16B swizzle.
// OUT_MODE: 0 = fp32 (+opt residual), 1 = fp16,
//           2 = fp16 exp(v) + per-(row,CTA) partial sums into zp,
//           3 = fp16-in, fp32-out... no: row-scaled by 1/Z (Z from zp) -> fp16.
#define STG_A 16384
#define STG_AB 32768
#define NSTAGE 3
#define SMEM_SZ (NSTAGE * STG_AB)   // 98304

template <int BIAS_MODE, bool HAS_RES, int OUT_MODE>
__global__ __launch_bounds__(256, 2) void tgemm(
    const fp16* __restrict__ Ah, const fp16* __restrict__ Bh,
    float* __restrict__ Cf, fp16* __restrict__ Oh,
    int K, int lda, int ldb, int ldc,
    size_t sA, size_t sB, size_t sC,
    const float* __restrict__ bias, const float* __restrict__ res, size_t sRes,
    float* __restrict__ zp, float scale) {
    extern __shared__ char smem[];
    const uint32_t sb = s2u(smem);
    const int tid = threadIdx.x, wid = tid >> 5, lane = tid & 31;
    const int m0 = blockIdx.y * 128, n0 = blockIdx.x * 128, b = blockIdx.z;
    const int wm = (wid >> 2) * 64, wn = (wid & 3) * 32;

    const char* Ap0 = (const char*)(Ah + (size_t)b * sA + (size_t)m0 * lda);
    const char* Bp0 = (const char*)(Bh + (size_t)b * sB + (size_t)n0 * ldb);

    const int S = K >> 6;
    const size_t la2 = (size_t)lda * 2, lb2 = (size_t)ldb * 2;

    auto load = [&](int s, int buf) {
        size_t kb = (size_t)s << 7;  // k0*2 bytes
        const char* Ap = Ap0 + kb;
        const char* Bp = Bp0 + kb;
        uint32_t ab = sb + buf * STG_AB;
        uint32_t bb = ab + STG_A;
#pragma unroll
        for (int j = 0; j < 4; j++) {
            int g = tid + j * 256;
            int r = g >> 3, c = g & 7;
            uint32_t sw = (uint32_t)(r * 128 + ((c ^ (r & 7)) << 4));
            cp16(ab + sw, Ap + (size_t)r * la2 + c * 16);
            cp16(bb + sw, Bp + (size_t)r * lb2 + c * 16);
        }
    };

    float acc[4][4][4];
#pragma unroll
    for (int i = 0; i < 4; i++)
#pragma unroll
        for (int j = 0; j < 4; j++)
#pragma unroll
            for (int q = 0; q < 4; q++) acc[i][j][q] = 0.f;

    // prologue: two stages in flight
    load(0, 0);
    asm volatile("cp.async.commit_group;");
    load(1, 1);
    asm volatile("cp.async.commit_group;");

    int cur = 0;
    for (int s = 0; s < S; s++) {
        asm volatile("cp.async.wait_group 1;");  // all but newest group landed
        __syncthreads();
        if (s + 2 < S) load(s + 2, (cur + 2) % NSTAGE);
        asm volatile("cp.async.commit_group;");  // empty commits keep window exact
        const uint32_t ab = sb + cur * STG_AB;
        const uint32_t bb = ab + STG_A;
#pragma unroll
        for (int kk = 0; kk < 4; kk++) {
            uint32_t af[4][4], bfr[2][4];
#pragma unroll
            for (int mi = 0; mi < 4; mi++) {
                int r = wm + mi * 16 + (lane & 15);
                int c = kk * 2 + (lane >> 4);
                LDSM4(af[mi], ab + r * 128 + ((c ^ (r & 7)) << 4));
            }
#pragma unroll
            for (int nj = 0; nj < 2; nj++) {
                int r = wn + nj * 16 + (lane & 7) + ((lane >> 4) << 3);
                int c = kk * 2 + ((lane >> 3) & 1);
                LDSM4(bfr[nj], bb + r * 128 + ((c ^ (r & 7)) << 4));
            }
#pragma unroll
            for (int mi = 0; mi < 4; mi++)
#pragma unroll
                for (int nj = 0; nj < 2; nj++) {
                    MMA16816(acc[mi][nj * 2 + 0], af[mi], bfr[nj][0], bfr[nj][1]);
                    MMA16816(acc[mi][nj * 2 + 1], af[mi], bfr[nj][2], bfr[nj][3]);
                }
        }
        cur = (cur + 1 == NSTAGE) ? 0 : cur + 1;
    }

    // ---------------- epilogue (register accumulators -> global) -----------
    const int qr = lane >> 2, qc = (lane & 3) * 2;

    // OUT_MODE 3: per-row 1/Z from 16 partials
    float rz[4][2];
    if (OUT_MODE == 3) {
#pragma unroll
        for (int mi = 0; mi < 4; mi++)
#pragma unroll
            for (int h = 0; h < 2; h++) {
                int m = m0 + wm + mi * 16 + h * 8 + qr;
                const float4* z4 = (const float4*)(zp + ((size_t)b * Tn + m) * 16);
                float4 a = z4[0], b4 = z4[1], c4 = z4[2], d4 = z4[3];
                float z = (a.x + a.y + a.z + a.w) + (b4.x + b4.y + b4.z + b4.w) +
                          (c4.x + c4.y + c4.z + c4.w) + (d4.x + d4.y + d4.z + d4.w);
                rz[mi][h] = 1.f / z;
            }
    }

    float rsum[4][2];
    if (OUT_MODE == 2) {
#pragma unroll
        for (int mi = 0; mi < 4; mi++)
#pragma unroll
            for (int h = 0; h < 2; h++) rsum[mi][h] = 0.f;
    }

#pragma unroll
    for (int mi = 0; mi < 4; mi++) {
#pragma unroll
        for (int ni = 0; ni < 4; ni++) {
            const int mA = m0 + wm + mi * 16 + qr;
            const int nA = n0 + wn + ni * 8 + qc;
#pragma unroll
            for (int h = 0; h < 2; h++) {
                const int m = mA + h * 8;
                float v0 = acc[mi][ni][h * 2 + 0] * scale;
                float v1 = acc[mi][ni][h * 2 + 1] * scale;
                if (BIAS_MODE == 1) { float bv = bias[m]; v0 += bv; v1 += bv; }
                if (BIAS_MODE == 2) { v0 += bias[nA]; v1 += bias[nA + 1]; }
                const size_t go = (size_t)m * ldc + nA;
                if (OUT_MODE == 2) {
                    v0 = __expf(v0);
                    v1 = __expf(v1);
                    rsum[mi][h] += v0 + v1;
                    __align__(4) fp16 ph[2] = {__float2half_rn(v0), __float2half_rn(v1)};
                    *(uint32_t*)(Oh + (size_t)b * sC + go) = *(uint32_t*)ph;
                } else if (OUT_MODE == 3) {
                    v0 *= rz[mi][h];
                    v1 *= rz[mi][h];
                    __align__(4) fp16 ph[2] = {__float2half_rn(v0), __float2half_rn(v1)};
                    *(uint32_t*)(Oh + (size_t)b * sC + go) = *(uint32_t*)ph;
                } else if (OUT_MODE == 1) {
                    __align__(4) fp16 ph[2] = {__float2half_rn(v0), __float2half_rn(v1)};
                    *(uint32_t*)(Oh + (size_t)b * sC + go) = *(uint32_t*)ph;
                } else {
                    if (HAS_RES) {
                        float2 r2 = *(const float2*)(res + (size_t)b * sRes + go);
                        v0 += r2.x; v1 += r2.y;
                    }
                    float2 o2 = {v0, v1};
                    *(float2*)(Cf + (size_t)b * sC + go) = o2;
                }
            }
        }
    }

    if (OUT_MODE == 2) {
        // reduce row partial across the 4 lanes sharing a row (lane&3)
#pragma unroll
        for (int mi = 0; mi < 4; mi++)
#pragma unroll
            for (int h = 0; h < 2; h++) {
                float v = rsum[mi][h];
                v += __shfl_xor_sync(0xffffffffu, v, 1);
                v += __shfl_xor_sync(0xffffffffu, v, 2);
                rsum[mi][h] = v;
            }
        __syncthreads();  // mainloop smem no longer needed
        float* zsm = (float*)smem;  // [128][4]
        if ((lane & 3) == 0) {
#pragma unroll
            for (int mi = 0; mi < 4; mi++)
#pragma unroll
                for (int h = 0; h < 2; h++) {
                    int r = wm + mi * 16 + h * 8 + qr;
                    zsm[r * 4 + (wid & 3)] = rsum[mi][h];
                }
        }
        __syncthreads();
        if (tid < 128) {
            float z = zsm[tid * 4] + zsm[tid * 4 + 1] + zsm[tid * 4 + 2] + zsm[tid * 4 + 3];
            zp[((size_t)b * Tn + m0 + tid) * 16 + blockIdx.x] = z;
        }
    }
}

// ---------------- launch ----------------------------------------------------
// Resolve the BASE symbol only; interior offsets computed host-side.
template <typename T>
static T* sym_base(const void* sym) {
    void* p = nullptr;
    cudaGetSymbolAddress(&p, sym);
    return (T*)p;
}

extern "C" void kernel_launch(void* const* d_in, const int* in_sizes, int n_in,
                              void* d_out, int out_size) {
    const float* x = (const float*)d_in[0];
    const float* gamma = (const float*)d_in[1];
    const float* beta = (const float*)d_in[2];
    const float* q_w = (const float*)d_in[3];
    const float* q_b = (const float*)d_in[4];
    const float* k_w = (const float*)d_in[5];
    const float* k_b = (const float*)d_in[6];
    const float* v_w = (const float*)d_in[7];
    const float* v_b = (const float*)d_in[8];
    const float* o_w = (const float*)d_in[9];
    const float* o_b = (const float*)d_in[10];
    float* out = (float*)d_out;

    cudaFuncSetAttribute(tgemm<2, false, 1>, cudaFuncAttributeMaxDynamicSharedMemorySize, SMEM_SZ);
    cudaFuncSetAttribute(tgemm<1, false, 1>, cudaFuncAttributeMaxDynamicSharedMemorySize, SMEM_SZ);
    cudaFuncSetAttribute(tgemm<0, false, 2>, cudaFuncAttributeMaxDynamicSharedMemorySize, SMEM_SZ);
    cudaFuncSetAttribute(tgemm<0, false, 3>, cudaFuncAttributeMaxDynamicSharedMemorySize, SMEM_SZ);
    cudaFuncSetAttribute(tgemm<1, true, 0>, cudaFuncAttributeMaxDynamicSharedMemorySize, SMEM_SZ);

    fp16* hT = sym_base<fp16>(g_hT);
    fp16* wqk = sym_base<fp16>(g_wqk);
    fp16* wv = sym_base<fp16>(g_wv);
    fp16* wo = sym_base<fp16>(g_wo);
    fp16* qk = sym_base<fp16>(g_qk);
    fp16* vv = sym_base<fp16>(g_vv);
    fp16* aT = sym_base<fp16>(g_aT);
    fp16* wt = sym_base<fp16>(g_wt);
    float* zp = sym_base<float>(g_zp);
    float* qkb = sym_base<float>(g_qkb);

    // 0: GN stats  1: GN apply+transpose  2: weights convert
    gn_stats<<<Bn * 32, 256>>>(x);
    happly<<<dim3(Tn / 32, Cn / 32, Bn), dim3(32, 8)>>>(x, gamma, beta);
    wconv<<<(4 * Cn * Cn + 255) / 256, 256>>>(q_w, k_w, v_w, o_w, q_b, k_b);

    // 3: merged Q|K projection -> qk[B,T,1024] fp16
    dim3 gQK(QKC / 128, Tn / 128, Bn);
    tgemm<2, false, 1><<<gQK, 256, SMEM_SZ>>>(
        hT, wqk, nullptr, qk,
        Cn, Cn, Cn, QKC, CT, 0, QKT, qkb, nullptr, 0, nullptr, 1.f);

    // 4: V projection -> vv [C,T] fp16
    dim3 gV(Tn / 128, Cn / 128, Bn);
    tgemm<1, false, 1><<<gV, 256, SMEM_SZ>>>(
        wv, hT, nullptr, vv,
        Cn, Cn, Cn, Tn, 0, CT, CT, v_b, nullptr, 0, nullptr, 1.f);

    // 5: Scores -> E = exp(S) fp16 + row partial sums (ncu capture slot)
    dim3 gS(Tn / 128, Tn / 128, Bn);
    tgemm<0, false, 2><<<gS, 256, SMEM_SZ>>>(
        qk, qk + Cn, nullptr, wt,
        Cn, QKC, QKC, Tn, QKT, QKT, TT, nullptr, nullptr, 0, zp,
        1.f / sqrtf((float)Cn));

    // 6: Attn*V with per-row 1/Z normalization -> aT fp16
    dim3 gA(Cn / 128, Tn / 128, Bn);
    tgemm<0, false, 3><<<gA, 256, SMEM_SZ>>>(
        wt, vv, nullptr, aT,
        Tn, Tn, Tn, Cn, TT, CT, CT, nullptr, nullptr, 0, zp, 1.f);

    // 7: Out proj + bias + residual -> out fp32
    dim3 gO(Tn / 128, Cn / 128, Bn);
    tgemm<1, true, 0><<<gO, 256, SMEM_SZ>>>(
        wo, aT, out, nullptr,
        Cn, Cn, Cn, Tn, 0, CT, CT, o_b, x, CT, nullptr, 1.f);
}

// round 11
// speedup vs baseline: 8.0176x; 1.0415x over previous
#include <cuda_runtime.h>
#include <cuda_fp16.h>
#include <math.h>
#include <stdint.h>

#define Bn 8
#define Cn 512
#define Tn 2048
#define CT ((size_t)Cn * Tn)
#define TT ((size_t)Tn * Tn)
#define QKC 1024                         // stacked q|k channel dim
#define QKT ((size_t)Tn * QKC)           // per-batch qk plane

typedef __half fp16;

// ---------------- scratch (static device globals; allocation-guard safe) ----
__device__ __align__(16) fp16 g_hT[Bn * Tn * Cn];    // [B,T,C] groupnormed, fp16
__device__ __align__(16) fp16 g_wqk[QKC * Cn];       // [Wq;Wk] fp16
__device__ __align__(16) fp16 g_wv[Cn * Cn];
__device__ __align__(16) fp16 g_wo[Cn * Cn];
__device__ __align__(16) float g_qkb[QKC];           // [q_b;k_b]
__device__ __align__(16) fp16 g_qk[Bn * Tn * QKC];   // [B,T,1024] q|k
__device__ __align__(16) fp16 g_vv[Bn * Cn * Tn];    // [B,C,T]
__device__ __align__(16) fp16 g_aT[Bn * Tn * Cn];    // [B,T,C]
__device__ __align__(16) fp16 g_wt[Bn * Tn * Tn];    // E = exp(scores), unnormalized
__device__ __align__(16) float g_zp[(size_t)Bn * Tn * 16];  // row-sum partials
__device__ __align__(16) float g_mean[Bn * 32];
__device__ __align__(16) float g_inv[Bn * 32];

// ---------------- PTX helpers ----------------------------------------------
__device__ __forceinline__ uint32_t s2u(const void* p) {
    uint32_t a;
    asm("{ .reg .u64 t; cvta.to.shared.u64 t, %1; cvt.u32.u64 %0, t; }"
        : "=r"(a) : "l"(p));
    return a;
}

__device__ __forceinline__ void cp16(uint32_t d, const void* s) {
    asm volatile("cp.async.cg.shared.global [%0], [%1], 16;" :: "r"(d), "l"(s) : "memory");
}

#define LDSM4(r, addr)                                                          \
    asm volatile("ldmatrix.sync.aligned.m8n8.x4.shared.b16 {%0,%1,%2,%3}, [%4];"\
        : "=r"((r)[0]), "=r"((r)[1]), "=r"((r)[2]), "=r"((r)[3]) : "r"(addr))

#define MMA16816(d, a, b0, b1)                                                  \
    asm volatile(                                                               \
        "mma.sync.aligned.m16n8k16.row.col.f32.f16.f16.f32 "                    \
        "{%0,%1,%2,%3}, {%4,%5,%6,%7}, {%8,%9}, {%0,%1,%2,%3};"                 \
        : "+f"((d)[0]), "+f"((d)[1]), "+f"((d)[2]), "+f"((d)[3])                \
        : "r"((a)[0]), "r"((a)[1]), "r"((a)[2]), "r"((a)[3]),                   \
          "r"(b0), "r"(b1))

// ---------------- GroupNorm stats -------------------------------------------
__global__ void gn_stats(const float* __restrict__ x) {
    const int bg = blockIdx.x, tid = threadIdx.x;
    const int b = bg >> 5, g = bg & 31;
    const size_t base = ((size_t)b * Cn + g * 16) * Tn;
    const float4* xv = (const float4*)(x + base);
    float s = 0.f, ss = 0.f;
    for (int i = tid; i < 8192; i += 256) {
        float4 v = xv[i];
        s += v.x + v.y + v.z + v.w;
        ss += v.x * v.x + v.y * v.y + v.z * v.z + v.w * v.w;
    }
    __shared__ float rs[256], rq[256];
    rs[tid] = s; rq[tid] = ss;
    __syncthreads();
    for (int o = 128; o > 0; o >>= 1) {
        if (tid < o) { rs[tid] += rs[tid + o]; rq[tid] += rq[tid + o]; }
        __syncthreads();
    }
    if (tid == 0) {
        float mean = rs[0] / 32768.f;
        float var = rq[0] / 32768.f - mean * mean;
        g_mean[bg] = mean;
        g_inv[bg] = rsqrtf(var + 1e-6f);
    }
}

// ---------------- GN apply + transpose -> fp16:  x[C,T] -> hT[T,C] ----------
__global__ void happly(const float* __restrict__ x, const float* __restrict__ gamma,
                       const float* __restrict__ beta) {
    __shared__ float tl[32][33];
    const int b = blockIdx.z, t0 = blockIdx.x * 32, c0 = blockIdx.y * 32;
    const int tx = threadIdx.x, ty = threadIdx.y;
#pragma unroll
    for (int k = 0; k < 4; k++) {
        int c = c0 + ty + k * 8;
        float ga = gamma[c] * g_inv[b * 32 + (c >> 4)];
        float be = beta[c] - g_mean[b * 32 + (c >> 4)] * ga;
        float v = x[((size_t)b * Cn + c) * Tn + t0 + tx];
        tl[ty + k * 8][tx] = v * ga + be;
    }
    __syncthreads();
#pragma unroll
    for (int k = 0; k < 4; k++) {
        int t = t0 + ty + k * 8;
        size_t o = ((size_t)b * Tn + t) * Cn + c0 + tx;
        g_hT[o] = __float2half_rn(tl[tx][ty + k * 8]);
    }
}

// ------- weights -> fp16 + qk bias concat, one launch -----------------------
__global__ void wconv(const float* __restrict__ qw, const float* __restrict__ kw,
                      const float* __restrict__ vw, const float* __restrict__ ow,
                      const float* __restrict__ qb, const float* __restrict__ kb) {
    const int n = Cn * Cn;
    int i = blockIdx.x * blockDim.x + threadIdx.x;
    if (i < QKC) g_qkb[i] = (i < Cn) ? qb[i] : kb[i - Cn];
    if (i >= 4 * n) return;
    int seg = i / n, j = i - seg * n;
    if (seg == 0)      g_wqk[j]     = __float2half_rn(qw[j]);
    else if (seg == 1) g_wqk[n + j] = __float2half_rn(kw[j]);
    else if (seg == 2) g_wv[j]      = __float2half_rn(vw[j]);
    else               g_wo[j]      = __float2half_rn(ow[j]);
}

// ---------------- mma.sync plain-fp16 GEMM, 3-stage pipeline ----------------
// D[m,n] = scale * A[m,k] * B[n,k]  (+bias +res)
// CTA tile 128x128, BK=64, 4 warps (2m x 2n), warp tile 64x64 (smem-AI fix).
// Both operands K-major; SMEM rows 128B with XOR-16B swizzle.
// OUT_MODE: 0 = fp32 (+opt residual), 1 = fp16,
//           2 = fp16 exp(v) + per-(row,CTA) partial sums into zp,
//           3 = row-scaled by 1/Z (Z from zp) -> fp16.
#define STG_A 16384
#define STG_AB 32768
#define NSTAGE 3
#define SMEM_SZ (NSTAGE * STG_AB)   // 98304
#define NTHR 128

template <int BIAS_MODE, bool HAS_RES, int OUT_MODE>
__global__ __launch_bounds__(NTHR, 2) void tgemm(
    const fp16* __restrict__ Ah, const fp16* __restrict__ Bh,
    float* __restrict__ Cf, fp16* __restrict__ Oh,
    int K, int lda, int ldb, int ldc,
    size_t sA, size_t sB, size_t sC,
    const float* __restrict__ bias, const float* __restrict__ res, size_t sRes,
    float* __restrict__ zp, float scale) {
    extern __shared__ char smem[];
    const uint32_t sb = s2u(smem);
    const int tid = threadIdx.x, wid = tid >> 5, lane = tid & 31;
    const int m0 = blockIdx.y * 128, n0 = blockIdx.x * 128, b = blockIdx.z;
    const int wm = (wid >> 1) * 64, wn = (wid & 1) * 64;

    const char* Ap0 = (const char*)(Ah + (size_t)b * sA + (size_t)m0 * lda);
    const char* Bp0 = (const char*)(Bh + (size_t)b * sB + (size_t)n0 * ldb);

    const int S = K >> 6;
    const size_t la2 = (size_t)lda * 2, lb2 = (size_t)ldb * 2;

    auto load = [&](int s, int buf) {
        size_t kb = (size_t)s << 7;  // k0*2 bytes
        const char* Ap = Ap0 + kb;
        const char* Bp = Bp0 + kb;
        uint32_t ab = sb + buf * STG_AB;
        uint32_t bb = ab + STG_A;
#pragma unroll
        for (int j = 0; j < 8; j++) {
            int g = tid + j * NTHR;
            int r = g >> 3, c = g & 7;
            uint32_t sw = (uint32_t)(r * 128 + ((c ^ (r & 7)) << 4));
            cp16(ab + sw, Ap + (size_t)r * la2 + c * 16);
            cp16(bb + sw, Bp + (size_t)r * lb2 + c * 16);
        }
    };

    float acc[4][8][4];
#pragma unroll
    for (int i = 0; i < 4; i++)
#pragma unroll
        for (int j = 0; j < 8; j++)
#pragma unroll
            for (int q = 0; q < 4; q++) acc[i][j][q] = 0.f;

    // prologue: two stages in flight
    load(0, 0);
    asm volatile("cp.async.commit_group;");
    load(1, 1);
    asm volatile("cp.async.commit_group;");

    int cur = 0;
    for (int s = 0; s < S; s++) {
        asm volatile("cp.async.wait_group 1;");  // all but newest group landed
        __syncthreads();
        if (s + 2 < S) load(s + 2, (cur + 2) % NSTAGE);
        asm volatile("cp.async.commit_group;");  // empty commits keep window exact
        const uint32_t ab = sb + cur * STG_AB;
        const uint32_t bb = ab + STG_A;
#pragma unroll
        for (int kk = 0; kk < 4; kk++) {
            uint32_t af[4][4], bfr[4][4];
#pragma unroll
            for (int mi = 0; mi < 4; mi++) {
                int r = wm + mi * 16 + (lane & 15);
                int c = kk * 2 + (lane >> 4);
                LDSM4(af[mi], ab + r * 128 + ((c ^ (r & 7)) << 4));
            }
#pragma unroll
            for (int nj = 0; nj < 4; nj++) {
                int r = wn + nj * 16 + (lane & 7) + ((lane >> 4) << 3);
                int c = kk * 2 + ((lane >> 3) & 1);
                LDSM4(bfr[nj], bb + r * 128 + ((c ^ (r & 7)) << 4));
            }
#pragma unroll
            for (int mi = 0; mi < 4; mi++)
#pragma unroll
                for (int nj = 0; nj < 4; nj++) {
                    MMA16816(acc[mi][nj * 2 + 0], af[mi], bfr[nj][0], bfr[nj][1]);
                    MMA16816(acc[mi][nj * 2 + 1], af[mi], bfr[nj][2], bfr[nj][3]);
                }
        }
        cur = (cur + 1 == NSTAGE) ? 0 : cur + 1;
    }

    // ---------------- epilogue (register accumulators -> global) -----------
    const int qr = lane >> 2, qc = (lane & 3) * 2;

    // OUT_MODE 3: per-row 1/Z from 16 partials
    float rz[4][2];
    if (OUT_MODE == 3) {
#pragma unroll
        for (int mi = 0; mi < 4; mi++)
#pragma unroll
            for (int h = 0; h < 2; h++) {
                int m = m0 + wm + mi * 16 + h * 8 + qr;
                const float4* z4 = (const float4*)(zp + ((size_t)b * Tn + m) * 16);
                float4 a = z4[0], b4 = z4[1], c4 = z4[2], d4 = z4[3];
                float z = (a.x + a.y + a.z + a.w) + (b4.x + b4.y + b4.z + b4.w) +
                          (c4.x + c4.y + c4.z + c4.w) + (d4.x + d4.y + d4.z + d4.w);
                rz[mi][h] = 1.f / z;
            }
    }

    float rsum[4][2];
    if (OUT_MODE == 2) {
#pragma unroll
        for (int mi = 0; mi < 4; mi++)
#pragma unroll
            for (int h = 0; h < 2; h++) rsum[mi][h] = 0.f;
    }

#pragma unroll
    for (int mi = 0; mi < 4; mi++) {
#pragma unroll
        for (int ni = 0; ni < 8; ni++) {
            const int mA = m0 + wm + mi * 16 + qr;
            const int nA = n0 + wn + ni * 8 + qc;
#pragma unroll
            for (int h = 0; h < 2; h++) {
                const int m = mA + h * 8;
                float v0 = acc[mi][ni][h * 2 + 0] * scale;
                float v1 = acc[mi][ni][h * 2 + 1] * scale;
                if (BIAS_MODE == 1) { float bv = bias[m]; v0 += bv; v1 += bv; }
                if (BIAS_MODE == 2) { v0 += bias[nA]; v1 += bias[nA + 1]; }
                const size_t go = (size_t)m * ldc + nA;
                if (OUT_MODE == 2) {
                    v0 = __expf(v0);
                    v1 = __expf(v1);
                    rsum[mi][h] += v0 + v1;
                    __align__(4) fp16 ph[2] = {__float2half_rn(v0), __float2half_rn(v1)};
                    *(uint32_t*)(Oh + (size_t)b * sC + go) = *(uint32_t*)ph;
                } else if (OUT_MODE == 3) {
                    v0 *= rz[mi][h];
                    v1 *= rz[mi][h];
                    __align__(4) fp16 ph[2] = {__float2half_rn(v0), __float2half_rn(v1)};
                    *(uint32_t*)(Oh + (size_t)b * sC + go) = *(uint32_t*)ph;
                } else if (OUT_MODE == 1) {
                    __align__(4) fp16 ph[2] = {__float2half_rn(v0), __float2half_rn(v1)};
                    *(uint32_t*)(Oh + (size_t)b * sC + go) = *(uint32_t*)ph;
                } else {
                    if (HAS_RES) {
                        float2 r2 = *(const float2*)(res + (size_t)b * sRes + go);
                        v0 += r2.x; v1 += r2.y;
                    }
                    float2 o2 = {v0, v1};
                    *(float2*)(Cf + (size_t)b * sC + go) = o2;
                }
            }
        }
    }

    if (OUT_MODE == 2) {
        // reduce row partial across the 4 lanes sharing a row (lane&3)
#pragma unroll
        for (int mi = 0; mi < 4; mi++)
#pragma unroll
            for (int h = 0; h < 2; h++) {
                float v = rsum[mi][h];
                v += __shfl_xor_sync(0xffffffffu, v, 1);
                v += __shfl_xor_sync(0xffffffffu, v, 2);
                rsum[mi][h] = v;
            }
        __syncthreads();  // mainloop smem no longer needed
        float* zsm = (float*)smem;  // [128][2] : 2 n-warps per row group
        if ((lane & 3) == 0) {
#pragma unroll
            for (int mi = 0; mi < 4; mi++)
#pragma unroll
                for (int h = 0; h < 2; h++) {
                    int r = wm + mi * 16 + h * 8 + qr;
                    zsm[r * 2 + (wid & 1)] = rsum[mi][h];
                }
        }
        __syncthreads();
        float z = zsm[tid * 2] + zsm[tid * 2 + 1];
        zp[((size_t)b * Tn + m0 + tid) * 16 + blockIdx.x] = z;
    }
}

// ---------------- launch ----------------------------------------------------
// Resolve the BASE symbol only; interior offsets computed host-side.
template <typename T>
static T* sym_base(const void* sym) {
    void* p = nullptr;
    cudaGetSymbolAddress(&p, sym);
    return (T*)p;
}

extern "C" void kernel_launch(void* const* d_in, const int* in_sizes, int n_in,
                              void* d_out, int out_size) {
    const float* x = (const float*)d_in[0];
    const float* gamma = (const float*)d_in[1];
    const float* beta = (const float*)d_in[2];
    const float* q_w = (const float*)d_in[3];
    const float* q_b = (const float*)d_in[4];
    const float* k_w = (const float*)d_in[5];
    const float* k_b = (const float*)d_in[6];
    const float* v_w = (const float*)d_in[7];
    const float* v_b = (const float*)d_in[8];
    const float* o_w = (const float*)d_in[9];
    const float* o_b = (const float*)d_in[10];
    float* out = (float*)d_out;

    cudaFuncSetAttribute(tgemm<2, false, 1>, cudaFuncAttributeMaxDynamicSharedMemorySize, SMEM_SZ);
    cudaFuncSetAttribute(tgemm<1, false, 1>, cudaFuncAttributeMaxDynamicSharedMemorySize, SMEM_SZ);
    cudaFuncSetAttribute(tgemm<0, false, 2>, cudaFuncAttributeMaxDynamicSharedMemorySize, SMEM_SZ);
    cudaFuncSetAttribute(tgemm<0, false, 3>, cudaFuncAttributeMaxDynamicSharedMemorySize, SMEM_SZ);
    cudaFuncSetAttribute(tgemm<1, true, 0>, cudaFuncAttributeMaxDynamicSharedMemorySize, SMEM_SZ);

    fp16* hT = sym_base<fp16>(g_hT);
    fp16* wqk = sym_base<fp16>(g_wqk);
    fp16* wv = sym_base<fp16>(g_wv);
    fp16* wo = sym_base<fp16>(g_wo);
    fp16* qk = sym_base<fp16>(g_qk);
    fp16* vv = sym_base<fp16>(g_vv);
    fp16* aT = sym_base<fp16>(g_aT);
    fp16* wt = sym_base<fp16>(g_wt);
    float* zp = sym_base<float>(g_zp);
    float* qkb = sym_base<float>(g_qkb);

    // 0: GN stats  1: GN apply+transpose  2: weights convert
    gn_stats<<<Bn * 32, 256>>>(x);
    happly<<<dim3(Tn / 32, Cn / 32, Bn), dim3(32, 8)>>>(x, gamma, beta);
    wconv<<<(4 * Cn * Cn + 255) / 256, 256>>>(q_w, k_w, v_w, o_w, q_b, k_b);

    // 3: merged Q|K projection -> qk[B,T,1024] fp16
    dim3 gQK(QKC / 128, Tn / 128, Bn);
    tgemm<2, false, 1><<<gQK, NTHR, SMEM_SZ>>>(
        hT, wqk, nullptr, qk,
        Cn, Cn, Cn, QKC, CT, 0, QKT, qkb, nullptr, 0, nullptr, 1.f);

    // 4: V projection -> vv [C,T] fp16
    dim3 gV(Tn / 128, Cn / 128, Bn);
    tgemm<1, false, 1><<<gV, NTHR, SMEM_SZ>>>(
        wv, hT, nullptr, vv,
        Cn, Cn, Cn, Tn, 0, CT, CT, v_b, nullptr, 0, nullptr, 1.f);

    // 5: Scores -> E = exp(S) fp16 + row partial sums
    dim3 gS(Tn / 128, Tn / 128, Bn);
    tgemm<0, false, 2><<<gS, NTHR, SMEM_SZ>>>(
        qk, qk + Cn, nullptr, wt,
        Cn, QKC, QKC, Tn, QKT, QKT, TT, nullptr, nullptr, 0, zp,
        1.f / sqrtf((float)Cn));

    // 6: Attn*V with per-row 1/Z normalization -> aT fp16
    dim3 gA(Cn / 128, Tn / 128, Bn);
    tgemm<0, false, 3><<<gA, NTHR, SMEM_SZ>>>(
        wt, vv, nullptr, aT,
        Tn, Tn, Tn, Cn, TT, CT, CT, nullptr, nullptr, 0, zp, 1.f);

    // 7: Out proj + bias + residual -> out fp32
    dim3 gO(Tn / 128, Cn / 128, Bn);
    tgemm<1, true, 0><<<gO, NTHR, SMEM_SZ>>>(
        wo, aT, out, nullptr,
        Cn, Cn, Cn, Tn, 0, CT, CT, o_b, x, CT, nullptr, 1.f);
}